// round 8
// baseline (speedup 1.0000x reference)
#include <cuda_runtime.h>
#include <cstdint>

typedef unsigned long long ULL;

// Problem constants: B=128, T=1024, H=128, D=64, L=3
#define BB   128
#define TT   1024
#define HH   128
#define G4   512
#define MROWS (BB*TT)

// Scratch (device globals: allocation-rule-safe)
__device__ float g_xg[(size_t)MROWS * G4];   // 256 MB
__device__ float g_y [(size_t)MROWS * HH];   // 64 MB

// ---------------------------------------------------------------------------
// helpers
// ---------------------------------------------------------------------------
__device__ __forceinline__ void fma2(ULL& acc, ULL a, ULL b) {
    asm("fma.rn.f32x2 %0, %1, %2, %0;" : "+l"(acc) : "l"(a), "l"(b));
}
__device__ __forceinline__ ULL pk2(float lo, float hi) {
    ULL r; asm("mov.b64 %0, {%1, %2};" : "=l"(r) : "f"(lo), "f"(hi)); return r;
}
__device__ __forceinline__ void upk2(ULL v, float& lo, float& hi) {
    asm("mov.b64 {%0, %1}, %2;" : "=f"(lo), "=f"(hi) : "l"(v));
}
__device__ __forceinline__ float tanhapx(float x) {
    float y; asm("tanh.approx.f32 %0, %1;" : "=f"(y) : "f"(x)); return y;
}
__device__ __forceinline__ float sigapx(float x) {        // 1-MUFU sigmoid
    return fmaf(tanhapx(0.5f * x), 0.5f, 0.5f);
}
__device__ __forceinline__ uint32_t smem_u32(const void* p) {
    uint32_t a;
    asm("{ .reg .u64 t; cvta.to.shared.u64 t, %1; cvt.u32.u64 %0, t; }"
        : "=r"(a) : "l"(p));
    return a;
}
__device__ __forceinline__ uint32_t mapa_u32(uint32_t a, uint32_t rank) {
    uint32_t r;
    asm("mapa.shared::cluster.u32 %0, %1, %2;" : "=r"(r) : "r"(a), "r"(rank));
    return r;
}

// ---------------------------------------------------------------------------
// xg GEMM: g_xg[m, 0:512] = A[m, 0:K] @ W[512, K]^T + (bih + bhh)
// BM=BN=128, BK=8, 256 threads, 8x8 tile, f32x2; smem ping-pong (1 sync/chunk)
// (unchanged from R5 — passed)
// ---------------------------------------------------------------------------
template<int K>
__global__ __launch_bounds__(256, 2)
void xg_gemm(const float* __restrict__ Aext, int use_gy,
             const float* __restrict__ W,
             const float* __restrict__ bih,
             const float* __restrict__ bhh)
{
    const int BM = 128, BN = 128, BK = 8;
    __shared__ __align__(16) float As[2][BK][BM + 4];
    __shared__ __align__(16) float Bs[2][BK][BN + 4];

    const float* A = use_gy ? (const float*)g_y : Aext;
    float* out = g_xg;

    int tid = threadIdx.x;
    int tx = tid & 15, ty = tid >> 4;
    int m0 = blockIdx.y * BM, n0 = blockIdx.x * BN;

    int am = tid >> 1, ak = (tid & 1) * 4;
    int wn = tid >> 1, wk = (tid & 1) * 4;

    ULL acc[8][4];
#pragma unroll
    for (int i = 0; i < 8; i++)
#pragma unroll
        for (int j = 0; j < 4; j++) acc[i][j] = 0ULL;

    float4 a_ld = *(const float4*)(A + (size_t)(m0 + am) * K + ak);
    float4 b_ld = *(const float4*)(W + (size_t)(n0 + wn) * K + wk);
    As[0][ak + 0][am] = a_ld.x; As[0][ak + 1][am] = a_ld.y;
    As[0][ak + 2][am] = a_ld.z; As[0][ak + 3][am] = a_ld.w;
    Bs[0][wk + 0][wn] = b_ld.x; Bs[0][wk + 1][wn] = b_ld.y;
    Bs[0][wk + 2][wn] = b_ld.z; Bs[0][wk + 3][wn] = b_ld.w;
    __syncthreads();

    const int NC = K / BK;
#pragma unroll 2
    for (int c = 0; c < NC; ++c) {
        int cur = c & 1, nxt = cur ^ 1;
        if (c + 1 < NC) {
            a_ld = *(const float4*)(A + (size_t)(m0 + am) * K + (c + 1) * BK + ak);
            b_ld = *(const float4*)(W + (size_t)(n0 + wn) * K + (c + 1) * BK + wk);
        }

#pragma unroll
        for (int k = 0; k < BK; k++) {
            float4 t0 = *(const float4*)&As[cur][k][ty * 8];
            float4 t1 = *(const float4*)&As[cur][k][ty * 8 + 4];
            float av[8] = {t0.x, t0.y, t0.z, t0.w, t1.x, t1.y, t1.z, t1.w};
            const ulonglong2* bbp = (const ulonglong2*)(&Bs[cur][k][tx * 8]);
            ulonglong2 b01 = bbp[0];
            ulonglong2 b23 = bbp[1];
#pragma unroll
            for (int i = 0; i < 8; i++) {
                ULL ai = pk2(av[i], av[i]);
                fma2(acc[i][0], ai, b01.x);
                fma2(acc[i][1], ai, b01.y);
                fma2(acc[i][2], ai, b23.x);
                fma2(acc[i][3], ai, b23.y);
            }
        }

        if (c + 1 < NC) {
            As[nxt][ak + 0][am] = a_ld.x; As[nxt][ak + 1][am] = a_ld.y;
            As[nxt][ak + 2][am] = a_ld.z; As[nxt][ak + 3][am] = a_ld.w;
            Bs[nxt][wk + 0][wn] = b_ld.x; Bs[nxt][wk + 1][wn] = b_ld.y;
            Bs[nxt][wk + 2][wn] = b_ld.z; Bs[nxt][wk + 3][wn] = b_ld.w;
            __syncthreads();
        }
    }

    float bias[8];
#pragma unroll
    for (int j = 0; j < 8; j++) {
        int n = n0 + tx * 8 + j;
        bias[j] = bih[n] + bhh[n];
    }
#pragma unroll
    for (int i = 0; i < 8; i++) {
        size_t row = (size_t)(m0 + ty * 8 + i) * G4 + n0 + tx * 8;
#pragma unroll
        for (int j = 0; j < 4; j++) {
            float lo, hi; upk2(acc[i][j], lo, hi);
            float2 v = make_float2(lo + bias[2 * j], hi + bias[2 * j + 1]);
            *(float2*)(out + row + 2 * j) = v;
        }
    }
}

// ---------------------------------------------------------------------------
// Recurrent scan v8: 1024 threads (8 warps/SMSP for latency hiding).
// Cluster of 2 CTAs / 2 batch rows; rank r owns h-cols [r*64, r*64+64).
// Thread = (jp = tid&255 -> Whh row g*128+r*64+nn, kq = tid>>8 -> 32-k window).
// Weights: 32 fp32 = 16 packed ULL/thread. Per step per thread: 2 rows x
// 16 fma2. pre[4][256][2] k-partials; gate threads (4 warps of a peer-k
// group) sum 4 partials per gate.
// SYNC SKELETON: identical to R5 (proven): single mbar count=4, lane-0
// arrives, mid+end __syncthreads, off-path y/xg after end sync.
// ---------------------------------------------------------------------------
__global__ __launch_bounds__(1024, 1) __cluster_dims__(2, 1, 1)
void lstm_rec8(const float* __restrict__ whh,
               const float* __restrict__ h0l,
               const float* __restrict__ c0l,
               float* __restrict__ hNl,
               float* __restrict__ cNl)
{
    __shared__ __align__(16) float hbuf[2][2][132];  // [parity][row][n] padded
    __shared__ __align__(8)  float pre[4][256][2];   // [kq][jp][row]
    __shared__ __align__(8)  ULL   bar;

    const int tid = threadIdx.x;
    const int r   = blockIdx.x & 1;
    const int b0  = (blockIdx.x >> 1) * 2;

    const int kq = tid >> 8;            // k-quarter, 8-warp-group aligned
    const int jp = tid & 255;           // gate-row within rank slice
    const int g  = jp >> 6;
    const int nn = jp & 63;
    const int k0 = kq * 32;

    uint32_t bar_addr = smem_u32(&bar);
    uint32_t peer_bar = mapa_u32(bar_addr, (uint32_t)(r ^ 1));

    if (tid == 0) {
        asm volatile("mbarrier.init.shared.b64 [%0], %1;"
                     :: "r"(bar_addr), "r"(4) : "memory");
    }
    if (tid < 256) {
        int row = tid >> 7, n = tid & 127;
        hbuf[1][row][n] = h0l[(b0 + row) * HH + n];
    }

    // weights -> registers: one Whh row x 32-k window = 16 packed ULL
    const int row_w = g * 128 + r * 64 + nn;
    ULL w2[16];
    const ULL* wp = (const ULL*)(whh + (size_t)row_w * HH + k0);
#pragma unroll
    for (int i = 0; i < 16; i++) w2[i] = wp[i];

    // gate role: first 128 threads of kq group 2*(r^1) (peer k-half, 4 warps)
    const bool is_gate = (kq == 2 * (r ^ 1)) && (jp < 128);
    const int row_g = jp & 1;
    const int nn_g  = (jp >> 1) & 63;
    const int n_g   = r * 64 + nn_g;

    float c = 0.f, hlast = 0.f;
    const float* px = g_xg + ((size_t)(b0 + row_g) * TT) * G4 + n_g;
    float*       py = g_y  + ((size_t)(b0 + row_g) * TT) * HH + n_g;
    uint32_t ph0 = 0, ph1 = 0;
    float xc0=0,xc1=0,xc2=0,xc3=0, xn0=0,xn1=0,xn2=0,xn3=0;
    if (is_gate) {
        c   = c0l[(b0 + row_g) * HH + n_g];
        ph0 = mapa_u32(smem_u32(&hbuf[0][row_g][n_g]), (uint32_t)(r ^ 1));
        ph1 = mapa_u32(smem_u32(&hbuf[1][row_g][n_g]), (uint32_t)(r ^ 1));
        xc0 = px[0];        xc1 = px[128];        xc2 = px[256];        xc3 = px[384];
        xn0 = px[G4 + 0];   xn1 = px[G4 + 128];   xn2 = px[G4 + 256];   xn3 = px[G4 + 384];
    }

    __syncthreads();
    asm volatile("barrier.cluster.arrive.aligned;" ::: "memory");
    asm volatile("barrier.cluster.wait.aligned;"   ::: "memory");

    for (int t = 0; t < TT; ++t) {
        const int pr = (t + 1) & 1;              // parity holding h(t-1)

        if ((kq >> 1) != r && t > 0) {           // peer-k warps wait for h(t-1)
            unsigned par = (unsigned)((t - 1) & 1);
            asm volatile(
                "{\n\t"
                ".reg .pred P1;\n\t"
                "WLP%=:\n\t"
                "mbarrier.try_wait.parity.acquire.cluster.shared::cta.b64 P1, [%0], %1, 0x989680;\n\t"
                "@!P1 bra WLP%=;\n\t"
                "}"
                :: "r"(bar_addr), "r"(par) : "memory");
        }

        // matvec: this thread's 32-k window, both batch rows (2 x 16 fma2)
        ULL a00 = 0, a01 = 0, a10 = 0, a11 = 0;
        const ulonglong2* hv0 = (const ulonglong2*)&hbuf[pr][0][k0];
        const ulonglong2* hv1 = (const ulonglong2*)&hbuf[pr][1][k0];
#pragma unroll
        for (int i = 0; i < 8; i++) {
            ulonglong2 u0 = hv0[i], u1 = hv1[i];
            fma2(a00, w2[2 * i],     u0.x);
            fma2(a01, w2[2 * i + 1], u0.y);
            fma2(a10, w2[2 * i],     u1.x);
            fma2(a11, w2[2 * i + 1], u1.y);
        }
        float s0, s1;
        { float x0,x1,x2,x3; upk2(a00,x0,x1); upk2(a01,x2,x3); s0 = (x0+x1)+(x2+x3); }
        { float x0,x1,x2,x3; upk2(a10,x0,x1); upk2(a11,x2,x3); s1 = (x0+x1)+(x2+x3); }
        *(float2*)&pre[kq][jp][0] = make_float2(s0, s1);
        __syncthreads();                         // pre[] ready

        if (is_gate) {
            float p0 = 0.f, p1 = 0.f, p2 = 0.f, p3 = 0.f;
#pragma unroll
            for (int q = 0; q < 4; q++) {
                p0 += pre[q][      nn_g][row_g];
                p1 += pre[q][ 64 + nn_g][row_g];
                p2 += pre[q][128 + nn_g][row_g];
                p3 += pre[q][192 + nn_g][row_g];
            }
            float iv = sigapx(p0 + xc0);
            float fv = sigapx(p1 + xc1);
            float gv = tanhapx(p2 + xc2);
            float ov = sigapx(p3 + xc3);
            c = fv * c + iv * gv;
            float hh = ov * tanhapx(c);
            hlast = hh;
            // cross-CTA flight first
            uint32_t pa = (t & 1) ? ph1 : ph0;
            asm volatile("st.shared::cluster.f32 [%0], %1;"
                         :: "r"(pa), "f"(hh) : "memory");
            hbuf[t & 1][row_g][n_g] = hh;
            __syncwarp();
            if ((tid & 31) == 0) {
                asm volatile("mbarrier.arrive.release.cluster.shared::cluster.b64 _, [%0];"
                             :: "r"(peer_bar) : "memory");
            }
        }
        __syncthreads();                         // hbuf local half ready

        // off the critical path
        if (is_gate) {
            py[(size_t)t * HH] = hlast;
            float xf0 = 0, xf1 = 0, xf2 = 0, xf3 = 0;
            if (t + 2 < TT) {
                const float* p2p = px + (size_t)(t + 2) * G4;
                xf0 = p2p[0]; xf1 = p2p[128]; xf2 = p2p[256]; xf3 = p2p[384];
            }
            xc0 = xn0; xc1 = xn1; xc2 = xn2; xc3 = xn3;
            xn0 = xf0; xn1 = xf1; xn2 = xf2; xn3 = xf3;
        }
    }

    if (is_gate) {
        hNl[(b0 + row_g) * HH + n_g] = hlast;
        cNl[(b0 + row_g) * HH + n_g] = c;
    }
    asm volatile("barrier.cluster.arrive.aligned;" ::: "memory");
    asm volatile("barrier.cluster.wait.aligned;"   ::: "memory");
}

// ---------------------------------------------------------------------------
// Output projection: out[bt] = relu(y3[bt,:] . Wout + bout), one warp per row
// ---------------------------------------------------------------------------
__global__ __launch_bounds__(256)
void proj_kernel(const float* __restrict__ wout,
                 const float* __restrict__ bout,
                 float* __restrict__ out)
{
    int gwarp = (blockIdx.x * blockDim.x + threadIdx.x) >> 5;
    int lane  = threadIdx.x & 31;
    if (gwarp >= MROWS) return;
    float4 yv = ((const float4*)(g_y + (size_t)gwarp * HH))[lane];
    float4 wv = ((const float4*)wout)[lane];
    float s = yv.x * wv.x + yv.y * wv.y + yv.z * wv.z + yv.w * wv.w;
#pragma unroll
    for (int o = 16; o; o >>= 1) s += __shfl_xor_sync(0xFFFFFFFFu, s, o);
    if (lane == 0) out[gwarp] = fmaxf(s + bout[0], 0.f);
}

// ---------------------------------------------------------------------------
extern "C" void kernel_launch(void* const* d_in, const int* in_sizes, int n_in,
                              void* d_out, int out_size)
{
    const float* x    = (const float*)d_in[0];
    const float* h0   = (const float*)d_in[1];
    const float* c0   = (const float*)d_in[2];
    const float* Wih[3] = {(const float*)d_in[3], (const float*)d_in[7],  (const float*)d_in[11]};
    const float* Whh[3] = {(const float*)d_in[4], (const float*)d_in[8],  (const float*)d_in[12]};
    const float* bih[3] = {(const float*)d_in[5], (const float*)d_in[9],  (const float*)d_in[13]};
    const float* bhh[3] = {(const float*)d_in[6], (const float*)d_in[10], (const float*)d_in[14]};
    const float* Wout = (const float*)d_in[15];
    const float* bout = (const float*)d_in[16];

    float* out = (float*)d_out;           // [B*T]
    float* hN  = out + MROWS;             // [3,B,H]
    float* cN  = hN + 3 * BB * HH;        // [3,B,H]

    dim3 ggrid(G4 / 128, MROWS / 128);    // (4, 1024)

    xg_gemm<64><<<ggrid, 256>>>(x, 0, Wih[0], bih[0], bhh[0]);
    lstm_rec8<<<BB, 1024>>>(Whh[0], h0, c0, hN, cN);

    xg_gemm<128><<<ggrid, 256>>>(nullptr, 1, Wih[1], bih[1], bhh[1]);
    lstm_rec8<<<BB, 1024>>>(Whh[1], h0 + BB * HH, c0 + BB * HH,
                            hN + BB * HH, cN + BB * HH);

    xg_gemm<128><<<ggrid, 256>>>(nullptr, 1, Wih[2], bih[2], bhh[2]);
    lstm_rec8<<<BB, 1024>>>(Whh[2], h0 + 2 * BB * HH, c0 + 2 * BB * HH,
                            hN + 2 * BB * HH, cN + 2 * BB * HH);

    proj_kernel<<<MROWS / 8, 256>>>(Wout, bout, out);
}

// round 9
// speedup vs baseline: 1.1173x; 1.1173x over previous
#include <cuda_runtime.h>
#include <cstdint>

typedef unsigned long long ULL;

// Problem constants: B=128, T=1024, H=128, D=64, L=3
#define BB   128
#define TT   1024
#define HH   128
#define G4   512
#define MROWS (BB*TT)

// Scratch (device globals: allocation-rule-safe)
__device__ float g_xg[(size_t)MROWS * G4];   // 256 MB
__device__ float g_y [(size_t)MROWS * HH];   // 64 MB

// ---------------------------------------------------------------------------
// helpers
// ---------------------------------------------------------------------------
__device__ __forceinline__ void fma2(ULL& acc, ULL a, ULL b) {
    asm("fma.rn.f32x2 %0, %1, %2, %0;" : "+l"(acc) : "l"(a), "l"(b));
}
__device__ __forceinline__ ULL pk2(float lo, float hi) {
    ULL r; asm("mov.b64 %0, {%1, %2};" : "=l"(r) : "f"(lo), "f"(hi)); return r;
}
__device__ __forceinline__ void upk2(ULL v, float& lo, float& hi) {
    asm("mov.b64 {%0, %1}, %2;" : "=f"(lo), "=f"(hi) : "l"(v));
}
__device__ __forceinline__ float tanhapx(float x) {
    float y; asm("tanh.approx.f32 %0, %1;" : "=f"(y) : "f"(x)); return y;
}
__device__ __forceinline__ float sigapx(float x) {        // 1-MUFU sigmoid
    return fmaf(tanhapx(0.5f * x), 0.5f, 0.5f);
}
__device__ __forceinline__ uint32_t smem_u32(const void* p) {
    uint32_t a;
    asm("{ .reg .u64 t; cvta.to.shared.u64 t, %1; cvt.u32.u64 %0, t; }"
        : "=r"(a) : "l"(p));
    return a;
}
__device__ __forceinline__ uint32_t mapa_u32(uint32_t a, uint32_t rank) {
    uint32_t r;
    asm("mapa.shared::cluster.u32 %0, %1, %2;" : "=r"(r) : "r"(a), "r"(rank));
    return r;
}

// ---------------------------------------------------------------------------
// xg GEMM (unchanged from R5 — passed): g_xg = A @ W^T + (bih+bhh)
// BM=BN=128, BK=8, 256 threads, 8x8 tile, f32x2, smem ping-pong
// ---------------------------------------------------------------------------
template<int K>
__global__ __launch_bounds__(256, 2)
void xg_gemm(const float* __restrict__ Aext, int use_gy,
             const float* __restrict__ W,
             const float* __restrict__ bih,
             const float* __restrict__ bhh)
{
    const int BM = 128, BN = 128, BK = 8;
    __shared__ __align__(16) float As[2][BK][BM + 4];
    __shared__ __align__(16) float Bs[2][BK][BN + 4];

    const float* A = use_gy ? (const float*)g_y : Aext;
    float* out = g_xg;

    int tid = threadIdx.x;
    int tx = tid & 15, ty = tid >> 4;
    int m0 = blockIdx.y * BM, n0 = blockIdx.x * BN;

    int am = tid >> 1, ak = (tid & 1) * 4;
    int wn = tid >> 1, wk = (tid & 1) * 4;

    ULL acc[8][4];
#pragma unroll
    for (int i = 0; i < 8; i++)
#pragma unroll
        for (int j = 0; j < 4; j++) acc[i][j] = 0ULL;

    float4 a_ld = *(const float4*)(A + (size_t)(m0 + am) * K + ak);
    float4 b_ld = *(const float4*)(W + (size_t)(n0 + wn) * K + wk);
    As[0][ak + 0][am] = a_ld.x; As[0][ak + 1][am] = a_ld.y;
    As[0][ak + 2][am] = a_ld.z; As[0][ak + 3][am] = a_ld.w;
    Bs[0][wk + 0][wn] = b_ld.x; Bs[0][wk + 1][wn] = b_ld.y;
    Bs[0][wk + 2][wn] = b_ld.z; Bs[0][wk + 3][wn] = b_ld.w;
    __syncthreads();

    const int NC = K / BK;
#pragma unroll 2
    for (int c = 0; c < NC; ++c) {
        int cur = c & 1, nxt = cur ^ 1;
        if (c + 1 < NC) {
            a_ld = *(const float4*)(A + (size_t)(m0 + am) * K + (c + 1) * BK + ak);
            b_ld = *(const float4*)(W + (size_t)(n0 + wn) * K + (c + 1) * BK + wk);
        }

#pragma unroll
        for (int k = 0; k < BK; k++) {
            float4 t0 = *(const float4*)&As[cur][k][ty * 8];
            float4 t1 = *(const float4*)&As[cur][k][ty * 8 + 4];
            float av[8] = {t0.x, t0.y, t0.z, t0.w, t1.x, t1.y, t1.z, t1.w};
            const ulonglong2* bbp = (const ulonglong2*)(&Bs[cur][k][tx * 8]);
            ulonglong2 b01 = bbp[0];
            ulonglong2 b23 = bbp[1];
#pragma unroll
            for (int i = 0; i < 8; i++) {
                ULL ai = pk2(av[i], av[i]);
                fma2(acc[i][0], ai, b01.x);
                fma2(acc[i][1], ai, b01.y);
                fma2(acc[i][2], ai, b23.x);
                fma2(acc[i][3], ai, b23.y);
            }
        }

        if (c + 1 < NC) {
            As[nxt][ak + 0][am] = a_ld.x; As[nxt][ak + 1][am] = a_ld.y;
            As[nxt][ak + 2][am] = a_ld.z; As[nxt][ak + 3][am] = a_ld.w;
            Bs[nxt][wk + 0][wn] = b_ld.x; Bs[nxt][wk + 1][wn] = b_ld.y;
            Bs[nxt][wk + 2][wn] = b_ld.z; Bs[nxt][wk + 3][wn] = b_ld.w;
            __syncthreads();
        }
    }

    float bias[8];
#pragma unroll
    for (int j = 0; j < 8; j++) {
        int n = n0 + tx * 8 + j;
        bias[j] = bih[n] + bhh[n];
    }
#pragma unroll
    for (int i = 0; i < 8; i++) {
        size_t row = (size_t)(m0 + ty * 8 + i) * G4 + n0 + tx * 8;
#pragma unroll
        for (int j = 0; j < 4; j++) {
            float lo, hi; upk2(acc[i][j], lo, hi);
            float2 v = make_float2(lo + bias[2 * j], hi + bias[2 * j + 1]);
            *(float2*)(out + row + 2 * j) = v;
        }
    }
}

// ---------------------------------------------------------------------------
// Recurrent scan v9: cluster sync confined to the 4 gate warps.
// Cluster of 2 CTAs / 2 batch rows; rank r owns h-cols [r*64, r*64+64).
// Per step:
//   ALL warps: matvec (hbuf has BOTH halves) -> pre -> __syncthreads
//   gate warps (4): gates -> h; st.shared::cluster -> peer LANDING buf;
//     local hbuf own half; lane0 arrive.release on peer bar (count=4);
//     try_wait acquire OWN bar (peer's h landed); copy land -> hbuf peer half
//   __syncthreads  (matvec warps never touch the mbarrier)
//   off-path: y store, xg prefetch (gate warps)
// Send-before-wait on both CTAs; barrier used once/step, parity t&1.
// Landing buf parity-reuse separated >=2 steps by the h dependency chain.
// ---------------------------------------------------------------------------
__global__ __launch_bounds__(512, 1) __cluster_dims__(2, 1, 1)
void lstm_rec9(const float* __restrict__ whh,
               const float* __restrict__ h0l,
               const float* __restrict__ c0l,
               float* __restrict__ hNl,
               float* __restrict__ cNl)
{
    __shared__ __align__(16) float hbuf[2][2][132];  // [parity][row][n] padded
    __shared__ __align__(16) float land[2][2][66];   // [parity][row][nn] peer h
    __shared__ __align__(8)  float pre[2][512];      // [kh][jp*2 + row]
    __shared__ __align__(8)  ULL   bar;

    const int tid = threadIdx.x;
    const int r   = blockIdx.x & 1;
    const int b0  = (blockIdx.x >> 1) * 2;

    const int kh = tid >> 8;            // k-half for matvec
    const int jp = tid & 255;           // preact row within rank slice
    const int g  = jp >> 6;
    const int nn = jp & 63;

    uint32_t bar_addr = smem_u32(&bar);
    uint32_t peer_bar = mapa_u32(bar_addr, (uint32_t)(r ^ 1));

    if (tid == 0) {
        asm volatile("mbarrier.init.shared.b64 [%0], %1;"
                     :: "r"(bar_addr), "r"(4) : "memory");
    }
    // h(-1) = h0 at parity 1 (both halves, loaded locally)
    if (tid < 256) {
        int row = tid >> 7, n = tid & 127;
        hbuf[1][row][n] = h0l[(b0 + row) * HH + n];
    }

    // weights -> registers (R5 mapping: Whh row x k-half, 32 packed ULL)
    const int row_w = g * 128 + r * 64 + nn;
    ULL w2[32];
    const ULL* wp = (const ULL*)(whh + row_w * HH + kh * 64);
#pragma unroll
    for (int i = 0; i < 32; i++) w2[i] = wp[i];

    // gate role: first 128 threads of warp-group kh == r^1 (4 warps)
    const bool is_gate = (kh == (r ^ 1)) && (jp < 128);
    const int row_g = jp & 1;
    const int nn_g  = jp >> 1;          // [0,64)
    const int n_g   = r * 64 + nn_g;    // own n-half column

    float c = 0.f, hlast = 0.f;
    const float* px = g_xg + ((size_t)(b0 + row_g) * TT) * G4 + n_g;
    float*       py = g_y  + ((size_t)(b0 + row_g) * TT) * HH + n_g;
    uint32_t pl0 = 0, pl1 = 0;          // peer landing slots (2 parities)
    float xc0=0,xc1=0,xc2=0,xc3=0, xn0=0,xn1=0,xn2=0,xn3=0;
    if (is_gate) {
        c   = c0l[(b0 + row_g) * HH + n_g];
        pl0 = mapa_u32(smem_u32(&land[0][row_g][nn_g]), (uint32_t)(r ^ 1));
        pl1 = mapa_u32(smem_u32(&land[1][row_g][nn_g]), (uint32_t)(r ^ 1));
        xc0 = px[0];        xc1 = px[128];        xc2 = px[256];        xc3 = px[384];
        xn0 = px[G4 + 0];   xn1 = px[G4 + 128];   xn2 = px[G4 + 256];   xn3 = px[G4 + 384];
    }

    __syncthreads();
    asm volatile("barrier.cluster.arrive.aligned;" ::: "memory");
    asm volatile("barrier.cluster.wait.aligned;"   ::: "memory");

    for (int t = 0; t < TT; ++t) {
        const int pr = (t + 1) & 1;              // parity holding h(t-1)
        const int pw = t & 1;                    // parity to write h(t)

        // matvec: ALL warps, full h available in hbuf[pr]
        ULL a00 = 0, a01 = 0, a10 = 0, a11 = 0;
        const ulonglong2* hv0 = (const ulonglong2*)&hbuf[pr][0][kh * 64];
        const ulonglong2* hv1 = (const ulonglong2*)&hbuf[pr][1][kh * 64];
#pragma unroll
        for (int i = 0; i < 16; i++) {
            ulonglong2 u0 = hv0[i], u1 = hv1[i];
            fma2(a00, w2[2 * i],     u0.x);
            fma2(a01, w2[2 * i + 1], u0.y);
            fma2(a10, w2[2 * i],     u1.x);
            fma2(a11, w2[2 * i + 1], u1.y);
        }
        float s0, s1;
        { float x0,x1,x2,x3; upk2(a00,x0,x1); upk2(a01,x2,x3); s0 = (x0+x1)+(x2+x3); }
        { float x0,x1,x2,x3; upk2(a10,x0,x1); upk2(a11,x2,x3); s1 = (x0+x1)+(x2+x3); }
        *(float2*)&pre[kh][jp * 2] = make_float2(s0, s1);
        __syncthreads();                         // pre[] ready

        if (is_gate) {
            float pi = pre[0][(      nn_g) * 2 + row_g] + pre[1][(      nn_g) * 2 + row_g];
            float pf = pre[0][( 64 + nn_g) * 2 + row_g] + pre[1][( 64 + nn_g) * 2 + row_g];
            float pg = pre[0][(128 + nn_g) * 2 + row_g] + pre[1][(128 + nn_g) * 2 + row_g];
            float po = pre[0][(192 + nn_g) * 2 + row_g] + pre[1][(192 + nn_g) * 2 + row_g];
            float iv = sigapx(pi + xc0);
            float fv = sigapx(pf + xc1);
            float gv = tanhapx(pg + xc2);
            float ov = sigapx(po + xc3);
            c = fv * c + iv * gv;
            float hh = ov * tanhapx(c);
            hlast = hh;
            // send own half to peer's landing buffer (fire before waiting)
            uint32_t pa = pw ? pl1 : pl0;
            asm volatile("st.shared::cluster.f32 [%0], %1;"
                         :: "r"(pa), "f"(hh) : "memory");
            hbuf[pw][row_g][n_g] = hh;           // local own half
            __syncwarp();
            if ((tid & 31) == 0) {
                asm volatile("mbarrier.arrive.release.cluster.shared::cluster.b64 _, [%0];"
                             :: "r"(peer_bar) : "memory");
            }
            // wait for peer's h(t) to land (only these 4 warps ever wait)
            {
                unsigned par = (unsigned)(t & 1);
                asm volatile(
                    "{\n\t"
                    ".reg .pred P1;\n\t"
                    "WLP%=:\n\t"
                    "mbarrier.try_wait.parity.acquire.cluster.shared::cta.b64 P1, [%0], %1, 0x989680;\n\t"
                    "@!P1 bra WLP%=;\n\t"
                    "}"
                    :: "r"(bar_addr), "r"(par) : "memory");
            }
            // copy landed peer half into hbuf
            hbuf[pw][row_g][((r ^ 1) * 64) + nn_g] = land[pw][row_g][nn_g];
        }
        __syncthreads();                         // hbuf fully ready for t+1

        // off the critical path
        if (is_gate) {
            py[(size_t)t * HH] = hlast;
            float xf0 = 0, xf1 = 0, xf2 = 0, xf3 = 0;
            if (t + 2 < TT) {
                const float* p2 = px + (size_t)(t + 2) * G4;
                xf0 = p2[0]; xf1 = p2[128]; xf2 = p2[256]; xf3 = p2[384];
            }
            xc0 = xn0; xc1 = xn1; xc2 = xn2; xc3 = xn3;
            xn0 = xf0; xn1 = xf1; xn2 = xf2; xn3 = xf3;
        }
    }

    if (is_gate) {
        hNl[(b0 + row_g) * HH + n_g] = hlast;
        cNl[(b0 + row_g) * HH + n_g] = c;
    }
    asm volatile("barrier.cluster.arrive.aligned;" ::: "memory");
    asm volatile("barrier.cluster.wait.aligned;"   ::: "memory");
}

// ---------------------------------------------------------------------------
// Output projection: out[bt] = relu(y3[bt,:] . Wout + bout), one warp per row
// ---------------------------------------------------------------------------
__global__ __launch_bounds__(256)
void proj_kernel(const float* __restrict__ wout,
                 const float* __restrict__ bout,
                 float* __restrict__ out)
{
    int gwarp = (blockIdx.x * blockDim.x + threadIdx.x) >> 5;
    int lane  = threadIdx.x & 31;
    if (gwarp >= MROWS) return;
    float4 yv = ((const float4*)(g_y + (size_t)gwarp * HH))[lane];
    float4 wv = ((const float4*)wout)[lane];
    float s = yv.x * wv.x + yv.y * wv.y + yv.z * wv.z + yv.w * wv.w;
#pragma unroll
    for (int o = 16; o; o >>= 1) s += __shfl_xor_sync(0xFFFFFFFFu, s, o);
    if (lane == 0) out[gwarp] = fmaxf(s + bout[0], 0.f);
}

// ---------------------------------------------------------------------------
extern "C" void kernel_launch(void* const* d_in, const int* in_sizes, int n_in,
                              void* d_out, int out_size)
{
    const float* x    = (const float*)d_in[0];
    const float* h0   = (const float*)d_in[1];
    const float* c0   = (const float*)d_in[2];
    const float* Wih[3] = {(const float*)d_in[3], (const float*)d_in[7],  (const float*)d_in[11]};
    const float* Whh[3] = {(const float*)d_in[4], (const float*)d_in[8],  (const float*)d_in[12]};
    const float* bih[3] = {(const float*)d_in[5], (const float*)d_in[9],  (const float*)d_in[13]};
    const float* bhh[3] = {(const float*)d_in[6], (const float*)d_in[10], (const float*)d_in[14]};
    const float* Wout = (const float*)d_in[15];
    const float* bout = (const float*)d_in[16];

    float* out = (float*)d_out;           // [B*T]
    float* hN  = out + MROWS;             // [3,B,H]
    float* cN  = hN + 3 * BB * HH;        // [3,B,H]

    dim3 ggrid(G4 / 128, MROWS / 128);    // (4, 1024)

    xg_gemm<64><<<ggrid, 256>>>(x, 0, Wih[0], bih[0], bhh[0]);
    lstm_rec9<<<BB, 512>>>(Whh[0], h0, c0, hN, cN);

    xg_gemm<128><<<ggrid, 256>>>(nullptr, 1, Wih[1], bih[1], bhh[1]);
    lstm_rec9<<<BB, 512>>>(Whh[1], h0 + BB * HH, c0 + BB * HH,
                           hN + BB * HH, cN + BB * HH);

    xg_gemm<128><<<ggrid, 256>>>(nullptr, 1, Wih[2], bih[2], bhh[2]);
    lstm_rec9<<<BB, 512>>>(Whh[2], h0 + 2 * BB * HH, c0 + 2 * BB * HH,
                           hN + 2 * BB * HH, cN + 2 * BB * HH);

    proj_kernel<<<MROWS / 8, 256>>>(Wout, bout, out);
}

// round 10
// speedup vs baseline: 1.1729x; 1.0498x over previous
#include <cuda_runtime.h>
#include <cstdint>

typedef unsigned long long ULL;

// Problem constants: B=128, T=1024, H=128, D=64, L=3
#define BB   128
#define TT   1024
#define HH   128
#define G4   512
#define MROWS (BB*TT)
#define CHUNK 256
#define NCHUNK 4

// Scratch (device globals: allocation-rule-safe)
__device__ float g_xg[(size_t)MROWS * G4];   // 256 MB (recycled per layer-chunk)
__device__ float g_y [(size_t)MROWS * HH];   // 64 MB  (recycled per layer-chunk)

// ---------------------------------------------------------------------------
// helpers
// ---------------------------------------------------------------------------
__device__ __forceinline__ void fma2(ULL& acc, ULL a, ULL b) {
    asm("fma.rn.f32x2 %0, %1, %2, %0;" : "+l"(acc) : "l"(a), "l"(b));
}
__device__ __forceinline__ ULL pk2(float lo, float hi) {
    ULL r; asm("mov.b64 %0, {%1, %2};" : "=l"(r) : "f"(lo), "f"(hi)); return r;
}
__device__ __forceinline__ void upk2(ULL v, float& lo, float& hi) {
    asm("mov.b64 {%0, %1}, %2;" : "=f"(lo), "=f"(hi) : "l"(v));
}
__device__ __forceinline__ float tanhapx(float x) {
    float y; asm("tanh.approx.f32 %0, %1;" : "=f"(y) : "f"(x)); return y;
}
__device__ __forceinline__ float sigapx(float x) {
    return fmaf(tanhapx(0.5f * x), 0.5f, 0.5f);
}
__device__ __forceinline__ uint32_t smem_u32(const void* p) {
    uint32_t a;
    asm("{ .reg .u64 t; cvta.to.shared.u64 t, %1; cvt.u32.u64 %0, t; }"
        : "=r"(a) : "l"(p));
    return a;
}
__device__ __forceinline__ uint32_t mapa_u32(uint32_t a, uint32_t rank) {
    uint32_t r;
    asm("mapa.shared::cluster.u32 %0, %1, %2;" : "=r"(r) : "r"(a), "r"(rank));
    return r;
}

// ---------------------------------------------------------------------------
// init: copy h0,c0 -> state arrays (hN, cN in d_out region)
// ---------------------------------------------------------------------------
__global__ void init_state(const float* __restrict__ h0,
                           const float* __restrict__ c0,
                           float* __restrict__ hN, float* __restrict__ cN)
{
    int i = blockIdx.x * blockDim.x + threadIdx.x;
    if (i < 3 * BB * HH) { hN[i] = h0[i]; cN[i] = c0[i]; }
}

// ---------------------------------------------------------------------------
// Chunked xg GEMM: for chunk starting at t0, rows m = b*TT + t0 + tile*128.
// grid = (4, 256): by>>1 = b, by&1 = tile. Core identical to proven R5 GEMM.
// ---------------------------------------------------------------------------
template<int K>
__global__ __launch_bounds__(256, 2)
void xg_gemm_chunk(const float* __restrict__ Aext, int use_gy,
                   const float* __restrict__ W,
                   const float* __restrict__ bih,
                   const float* __restrict__ bhh,
                   int t0)
{
    const int BM = 128, BN = 128, BK = 8;
    __shared__ __align__(16) float As[2][BK][BM + 4];
    __shared__ __align__(16) float Bs[2][BK][BN + 4];

    const float* A = use_gy ? (const float*)g_y : Aext;
    float* out = g_xg;

    int tid = threadIdx.x;
    int tx = tid & 15, ty = tid >> 4;
    int m0 = (blockIdx.y >> 1) * TT + t0 + (blockIdx.y & 1) * BM;
    int n0 = blockIdx.x * BN;

    int am = tid >> 1, ak = (tid & 1) * 4;
    int wn = tid >> 1, wk = (tid & 1) * 4;

    ULL acc[8][4];
#pragma unroll
    for (int i = 0; i < 8; i++)
#pragma unroll
        for (int j = 0; j < 4; j++) acc[i][j] = 0ULL;

    float4 a_ld = *(const float4*)(A + (size_t)(m0 + am) * K + ak);
    float4 b_ld = *(const float4*)(W + (size_t)(n0 + wn) * K + wk);
    As[0][ak + 0][am] = a_ld.x; As[0][ak + 1][am] = a_ld.y;
    As[0][ak + 2][am] = a_ld.z; As[0][ak + 3][am] = a_ld.w;
    Bs[0][wk + 0][wn] = b_ld.x; Bs[0][wk + 1][wn] = b_ld.y;
    Bs[0][wk + 2][wn] = b_ld.z; Bs[0][wk + 3][wn] = b_ld.w;
    __syncthreads();

    const int NC = K / BK;
#pragma unroll 2
    for (int c = 0; c < NC; ++c) {
        int cur = c & 1, nxt = cur ^ 1;
        if (c + 1 < NC) {
            a_ld = *(const float4*)(A + (size_t)(m0 + am) * K + (c + 1) * BK + ak);
            b_ld = *(const float4*)(W + (size_t)(n0 + wn) * K + (c + 1) * BK + wk);
        }
#pragma unroll
        for (int k = 0; k < BK; k++) {
            float4 t0v = *(const float4*)&As[cur][k][ty * 8];
            float4 t1v = *(const float4*)&As[cur][k][ty * 8 + 4];
            float av[8] = {t0v.x, t0v.y, t0v.z, t0v.w, t1v.x, t1v.y, t1v.z, t1v.w};
            const ulonglong2* bbp = (const ulonglong2*)(&Bs[cur][k][tx * 8]);
            ulonglong2 b01 = bbp[0];
            ulonglong2 b23 = bbp[1];
#pragma unroll
            for (int i = 0; i < 8; i++) {
                ULL ai = pk2(av[i], av[i]);
                fma2(acc[i][0], ai, b01.x);
                fma2(acc[i][1], ai, b01.y);
                fma2(acc[i][2], ai, b23.x);
                fma2(acc[i][3], ai, b23.y);
            }
        }
        if (c + 1 < NC) {
            As[nxt][ak + 0][am] = a_ld.x; As[nxt][ak + 1][am] = a_ld.y;
            As[nxt][ak + 2][am] = a_ld.z; As[nxt][ak + 3][am] = a_ld.w;
            Bs[nxt][wk + 0][wn] = b_ld.x; Bs[nxt][wk + 1][wn] = b_ld.y;
            Bs[nxt][wk + 2][wn] = b_ld.z; Bs[nxt][wk + 3][wn] = b_ld.w;
            __syncthreads();
        }
    }

    float bias[8];
#pragma unroll
    for (int j = 0; j < 8; j++) {
        int n = n0 + tx * 8 + j;
        bias[j] = bih[n] + bhh[n];
    }
#pragma unroll
    for (int i = 0; i < 8; i++) {
        size_t row = (size_t)(m0 + ty * 8 + i) * G4 + n0 + tx * 8;
#pragma unroll
        for (int j = 0; j < 4; j++) {
            float lo, hi; upk2(acc[i][j], lo, hi);
            float2 v = make_float2(lo + bias[2 * j], hi + bias[2 * j + 1]);
            *(float2*)(out + row + 2 * j) = v;
        }
    }
}

// ---------------------------------------------------------------------------
// Recurrent chunk v10: R9-proven sync skeleton, 4 batch rows/cluster, chunked.
// grid = (64, n_lc). blockIdx.y selects (layer, t0). Cluster of 2 CTAs; rank
// r owns h-cols [r*64, r*64+64). 512 threads: kh = tid>>8 (k-half), jp =
// tid&255 -> Whh row g*128+r*64+nn; matvec loops the 4 batch rows.
// Gate group = full peer-k warp group (8 warps, 256 threads): unit =
// (row_g = jp&3, nn_g = jp>>2). mbar count 8, lane0 arrives. State h,c in
// gmem (hN/cN) between chunk launches.
// ---------------------------------------------------------------------------
__global__ __launch_bounds__(512, 1) __cluster_dims__(2, 1, 1)
void lstm_rec10(const float* __restrict__ whh0,
                const float* __restrict__ whh1,
                const float* __restrict__ whh2,
                float* __restrict__ hN, float* __restrict__ cN,
                int4 lsel, int4 tsel)
{
    __shared__ __align__(16) float hbuf[2][4][132];  // [parity][row][n]
    __shared__ __align__(16) float land[2][4][68];   // [parity][row][nn] peer h
    __shared__ __align__(16) float pre[2][256][4];   // [kh][jp][row]
    __shared__ __align__(8)  ULL   bar;

    const int lc = blockIdx.y;
    const int l  = (lc == 0) ? lsel.x : (lc == 1) ? lsel.y : lsel.z;
    const int t0 = (lc == 0) ? tsel.x : (lc == 1) ? tsel.y : tsel.z;
    const float* whh = (l == 0) ? whh0 : (l == 1) ? whh1 : whh2;
    float* hstate = hN + l * BB * HH;
    float* cstate = cN + l * BB * HH;

    const int tid = threadIdx.x;
    const int r   = blockIdx.x & 1;
    const int b0  = (blockIdx.x >> 1) * 4;

    const int kh = tid >> 8;
    const int jp = tid & 255;
    const int g  = jp >> 6;
    const int nn = jp & 63;

    uint32_t bar_addr = smem_u32(&bar);
    uint32_t peer_bar = mapa_u32(bar_addr, (uint32_t)(r ^ 1));

    if (tid == 0) {
        asm volatile("mbarrier.init.shared.b64 [%0], %1;"
                     :: "r"(bar_addr), "r"(8) : "memory");
    }
    // load h state (4 rows x 128) into parity-1 slot
    {
        int row = tid >> 7, n = tid & 127;
        hbuf[1][row][n] = hstate[(b0 + row) * HH + n];
    }

    // weights: one Whh row x k-half = 32 packed ULL
    const int row_w = g * 128 + r * 64 + nn;
    ULL w2[32];
    const ULL* wp = (const ULL*)(whh + (size_t)row_w * HH + kh * 64);
#pragma unroll
    for (int i = 0; i < 32; i++) w2[i] = wp[i];

    // gate role: ALL 256 threads of the peer-k warp group
    const bool is_gate = (kh == (r ^ 1));
    const int row_g = jp & 3;
    const int nn_g  = jp >> 2;           // [0,64)
    const int n_g   = r * 64 + nn_g;

    float c = 0.f, hlast = 0.f;
    const float* px = g_xg + ((size_t)(b0 + row_g) * TT) * G4 + n_g;
    float*       py = g_y  + ((size_t)(b0 + row_g) * TT) * HH + n_g;
    uint32_t pl0 = 0, pl1 = 0;
    float xc0=0,xc1=0,xc2=0,xc3=0, xn0=0,xn1=0,xn2=0,xn3=0;
    if (is_gate) {
        c   = cstate[(b0 + row_g) * HH + n_g];
        pl0 = mapa_u32(smem_u32(&land[0][row_g][nn_g]), (uint32_t)(r ^ 1));
        pl1 = mapa_u32(smem_u32(&land[1][row_g][nn_g]), (uint32_t)(r ^ 1));
        const float* p0 = px + (size_t)t0 * G4;
        xc0 = p0[0];        xc1 = p0[128];        xc2 = p0[256];        xc3 = p0[384];
        xn0 = p0[G4 + 0];   xn1 = p0[G4 + 128];   xn2 = p0[G4 + 256];   xn3 = p0[G4 + 384];
    }

    __syncthreads();
    asm volatile("barrier.cluster.arrive.aligned;" ::: "memory");
    asm volatile("barrier.cluster.wait.aligned;"   ::: "memory");

    for (int s = 0; s < CHUNK; ++s) {
        const int t  = t0 + s;
        const int pr = (s + 1) & 1;
        const int pw = s & 1;

        // matvec: all warps, 4 batch rows, this thread's 64-k half
        float s4[4];
#pragma unroll
        for (int rr = 0; rr < 4; rr += 2) {
            ULL a0 = 0, a1 = 0, c0_ = 0, c1_ = 0;
            const ulonglong2* hA = (const ulonglong2*)&hbuf[pr][rr][kh * 64];
            const ulonglong2* hB = (const ulonglong2*)&hbuf[pr][rr + 1][kh * 64];
#pragma unroll
            for (int i = 0; i < 16; i++) {
                ulonglong2 uA = hA[i], uB = hB[i];
                fma2(a0,  w2[2 * i],     uA.x);
                fma2(a1,  w2[2 * i + 1], uA.y);
                fma2(c0_, w2[2 * i],     uB.x);
                fma2(c1_, w2[2 * i + 1], uB.y);
            }
            float x0, x1, x2, x3;
            upk2(a0, x0, x1); upk2(a1, x2, x3);
            s4[rr] = (x0 + x1) + (x2 + x3);
            upk2(c0_, x0, x1); upk2(c1_, x2, x3);
            s4[rr + 1] = (x0 + x1) + (x2 + x3);
        }
        *(float4*)&pre[kh][jp][0] = make_float4(s4[0], s4[1], s4[2], s4[3]);
        __syncthreads();                          // pre[] ready

        if (is_gate) {
            float pi = pre[0][      nn_g][row_g] + pre[1][      nn_g][row_g];
            float pf = pre[0][ 64 + nn_g][row_g] + pre[1][ 64 + nn_g][row_g];
            float pg = pre[0][128 + nn_g][row_g] + pre[1][128 + nn_g][row_g];
            float po = pre[0][192 + nn_g][row_g] + pre[1][192 + nn_g][row_g];
            float iv = sigapx(pi + xc0);
            float fv = sigapx(pf + xc1);
            float gv = tanhapx(pg + xc2);
            float ov = sigapx(po + xc3);
            c = fv * c + iv * gv;
            float hh = ov * tanhapx(c);
            hlast = hh;
            // send own half to peer landing buffer, then arrive, then wait
            uint32_t pa = pw ? pl1 : pl0;
            asm volatile("st.shared::cluster.f32 [%0], %1;"
                         :: "r"(pa), "f"(hh) : "memory");
            hbuf[pw][row_g][n_g] = hh;
            __syncwarp();
            if ((tid & 31) == 0) {
                asm volatile("mbarrier.arrive.release.cluster.shared::cluster.b64 _, [%0];"
                             :: "r"(peer_bar) : "memory");
            }
            {
                unsigned par = (unsigned)(s & 1);
                asm volatile(
                    "{\n\t"
                    ".reg .pred P1;\n\t"
                    "WLP%=:\n\t"
                    "mbarrier.try_wait.parity.acquire.cluster.shared::cta.b64 P1, [%0], %1, 0x989680;\n\t"
                    "@!P1 bra WLP%=;\n\t"
                    "}"
                    :: "r"(bar_addr), "r"(par) : "memory");
            }
            hbuf[pw][row_g][((r ^ 1) * 64) + nn_g] = land[pw][row_g][nn_g];
        }
        __syncthreads();                          // hbuf fully ready for s+1

        // off the critical path: y store + xg prefetch (chunk-local clamp!)
        if (is_gate) {
            py[(size_t)t * HH] = hlast;
            float xf0 = 0, xf1 = 0, xf2 = 0, xf3 = 0;
            if (s + 2 < CHUNK) {
                const float* p2 = px + (size_t)(t + 2) * G4;
                xf0 = p2[0]; xf1 = p2[128]; xf2 = p2[256]; xf3 = p2[384];
            }
            xc0 = xn0; xc1 = xn1; xc2 = xn2; xc3 = xn3;
            xn0 = xf0; xn1 = xf1; xn2 = xf2; xn3 = xf3;
        }
    }

    if (is_gate) {
        hstate[(b0 + row_g) * HH + n_g] = hlast;
        cstate[(b0 + row_g) * HH + n_g] = c;
    }
    asm volatile("barrier.cluster.arrive.aligned;" ::: "memory");
    asm volatile("barrier.cluster.wait.aligned;"   ::: "memory");
}

// ---------------------------------------------------------------------------
// Output projection: out[bt] = relu(y3[bt,:] . Wout + bout), one warp per row
// ---------------------------------------------------------------------------
__global__ __launch_bounds__(256)
void proj_kernel(const float* __restrict__ wout,
                 const float* __restrict__ bout,
                 float* __restrict__ out)
{
    int gwarp = (blockIdx.x * blockDim.x + threadIdx.x) >> 5;
    int lane  = threadIdx.x & 31;
    if (gwarp >= MROWS) return;
    float4 yv = ((const float4*)(g_y + (size_t)gwarp * HH))[lane];
    float4 wv = ((const float4*)wout)[lane];
    float s = yv.x * wv.x + yv.y * wv.y + yv.z * wv.z + yv.w * wv.w;
#pragma unroll
    for (int o = 16; o; o >>= 1) s += __shfl_xor_sync(0xFFFFFFFFu, s, o);
    if (lane == 0) out[gwarp] = fmaxf(s + bout[0], 0.f);
}

// ---------------------------------------------------------------------------
// Diagonal-wave schedule: wave k runs rec_l chunk (k-l) concurrently in ONE
// launch, preceded by the gemm chunks it needs. g_xg/g_y rows recycle per
// layer with wave ordering guaranteeing read-before-overwrite.
// ---------------------------------------------------------------------------
extern "C" void kernel_launch(void* const* d_in, const int* in_sizes, int n_in,
                              void* d_out, int out_size)
{
    const float* x    = (const float*)d_in[0];
    const float* h0   = (const float*)d_in[1];
    const float* c0   = (const float*)d_in[2];
    const float* Wih[3] = {(const float*)d_in[3], (const float*)d_in[7],  (const float*)d_in[11]};
    const float* Whh[3] = {(const float*)d_in[4], (const float*)d_in[8],  (const float*)d_in[12]};
    const float* bih[3] = {(const float*)d_in[5], (const float*)d_in[9],  (const float*)d_in[13]};
    const float* bhh[3] = {(const float*)d_in[6], (const float*)d_in[10], (const float*)d_in[14]};
    const float* Wout = (const float*)d_in[15];
    const float* bout = (const float*)d_in[16];

    float* out = (float*)d_out;           // [B*T]
    float* hN  = out + MROWS;             // [3,B,H] = live state + final output
    float* cN  = hN + 3 * BB * HH;

    // state init
    init_state<<<(3 * BB * HH + 511) / 512, 512>>>(h0, c0, hN, cN);

    // layer-0 xg for all chunks (input x, K=64)
    for (int cch = 0; cch < NCHUNK; cch++)
        xg_gemm_chunk<64><<<dim3(4, 256), 256>>>(x, 0, Wih[0], bih[0], bhh[0],
                                                 cch * CHUNK);

    // diagonal waves k = 0 .. (NCHUNK-1)+2
    for (int k = 0; k <= NCHUNK - 1 + 2; k++) {
        // gemm wave: xg for layer l chunk (k-l), l = 1, 2
        if (k >= 1 && (k - 1) < NCHUNK)
            xg_gemm_chunk<128><<<dim3(4, 256), 256>>>(nullptr, 1, Wih[1],
                                                      bih[1], bhh[1],
                                                      (k - 1) * CHUNK);
        if (k >= 2 && (k - 2) < NCHUNK)
            xg_gemm_chunk<128><<<dim3(4, 256), 256>>>(nullptr, 1, Wih[2],
                                                      bih[2], bhh[2],
                                                      (k - 2) * CHUNK);
        // rec wave: one launch containing all (l, c = k-l) with 0 <= c < NCHUNK
        int ls[3], ts[3], n = 0;
        for (int l = 0; l < 3; l++) {
            int cc = k - l;
            if (cc >= 0 && cc < NCHUNK) { ls[n] = l; ts[n] = cc * CHUNK; n++; }
        }
        if (n > 0) {
            int4 lsel = make_int4(ls[0], n > 1 ? ls[1] : 0, n > 2 ? ls[2] : 0, 0);
            int4 tsel = make_int4(ts[0], n > 1 ? ts[1] : 0, n > 2 ? ts[2] : 0, 0);
            lstm_rec10<<<dim3(64, n), 512>>>(Whh[0], Whh[1], Whh[2],
                                             hN, cN, lsel, tsel);
        }
    }

    proj_kernel<<<MROWS / 8, 256>>>(Wout, bout, out);
}

// round 11
// speedup vs baseline: 1.2653x; 1.0788x over previous
#include <cuda_runtime.h>
#include <cstdint>

typedef unsigned long long ULL;

// Problem constants: B=128, T=1024, H=128, D=64, L=3
#define BB   128
#define TT   1024
#define HH   128
#define G4   512
#define MROWS (BB*TT)
#define CHUNK 512
#define NCHUNK 2

// Scratch (device globals: allocation-rule-safe)
__device__ float g_xg[(size_t)MROWS * G4];   // 256 MB (recycled per layer-chunk)
__device__ float g_y [(size_t)MROWS * HH];   // 64 MB  (recycled per layer-chunk)

// ---------------------------------------------------------------------------
// helpers
// ---------------------------------------------------------------------------
__device__ __forceinline__ void fma2(ULL& acc, ULL a, ULL b) {
    asm("fma.rn.f32x2 %0, %1, %2, %0;" : "+l"(acc) : "l"(a), "l"(b));
}
__device__ __forceinline__ void upk2(ULL v, float& lo, float& hi) {
    asm("mov.b64 {%0, %1}, %2;" : "=f"(lo), "=f"(hi) : "l"(v));
}
__device__ __forceinline__ float tanhapx(float x) {
    float y; asm("tanh.approx.f32 %0, %1;" : "=f"(y) : "f"(x)); return y;
}
__device__ __forceinline__ float sigapx(float x) {
    return fmaf(tanhapx(0.5f * x), 0.5f, 0.5f);
}
__device__ __forceinline__ uint32_t smem_u32(const void* p) {
    uint32_t a;
    asm("{ .reg .u64 t; cvta.to.shared.u64 t, %1; cvt.u32.u64 %0, t; }"
        : "=r"(a) : "l"(p));
    return a;
}
__device__ __forceinline__ uint32_t mapa_u32(uint32_t a, uint32_t rank) {
    uint32_t r;
    asm("mapa.shared::cluster.u32 %0, %1, %2;" : "=r"(r) : "r"(a), "r"(rank));
    return r;
}
__device__ __forceinline__ uint32_t f2tf32(float v) {
    uint32_t r; asm("cvt.rna.tf32.f32 %0, %1;" : "=r"(r) : "f"(v)); return r;
}
__device__ __forceinline__ void mma_tf32(float& c0, float& c1, float& c2, float& c3,
                                         uint32_t a0, uint32_t a1, uint32_t a2, uint32_t a3,
                                         uint32_t b0, uint32_t b1) {
    asm("mma.sync.aligned.m16n8k8.row.col.f32.tf32.tf32.f32 "
        "{%0,%1,%2,%3},{%4,%5,%6,%7},{%8,%9},{%0,%1,%2,%3};"
        : "+f"(c0), "+f"(c1), "+f"(c2), "+f"(c3)
        : "r"(a0), "r"(a1), "r"(a2), "r"(a3), "r"(b0), "r"(b1));
}

// ---------------------------------------------------------------------------
// init: copy h0,c0 -> state arrays (hN, cN in d_out region)
// ---------------------------------------------------------------------------
__global__ void init_state(const float* __restrict__ h0,
                           const float* __restrict__ c0,
                           float* __restrict__ hN, float* __restrict__ cN)
{
    int i = blockIdx.x * blockDim.x + threadIdx.x;
    if (i < 3 * BB * HH) { hN[i] = h0[i]; cN[i] = c0[i]; }
}

// ---------------------------------------------------------------------------
// 3xTF32 tensor-core GEMM: g_xg[m,:] = A[m,:K] @ W[512,K]^T + (bih+bhh)
// BM=BN=128, BK=8, 256 threads (8 warps as 2x4 of 64x32 warp tiles).
// A split a = hi + lo (cvt.rna.tf32); D = hi*hi + hi*lo + lo*hi (~fp32 acc).
// m0 = (by>>lg)*TT + t0 + (by & ((1<<lg)-1))*128 ; n0 = bx*128.
// Fragment layout (m16n8k8 tf32): a0=(g,t) a1=(g+8,t) a2=(g,t+4) a3=(g+8,t+4);
// b0=(k=t,n=g) b1=(k=t+4,n=g); c0=(g,2t) c1=(g,2t+1) c2/c3 at g+8.
// ---------------------------------------------------------------------------
template<int K>
__global__ __launch_bounds__(256, 2)
void xg_tf32(const float* __restrict__ Aext, int use_gy,
             const float* __restrict__ W,
             const float* __restrict__ bih,
             const float* __restrict__ bhh,
             int t0, int lg)
{
    __shared__ float Ahi[2][128][9], Alo[2][128][9];
    __shared__ float Bhi[2][128][9], Blo[2][128][9];

    const float* A = use_gy ? (const float*)g_y : Aext;

    const int tid  = threadIdx.x;
    const int lane = tid & 31;
    const int warp = tid >> 5;
    const int wm   = warp & 1;            // 2 row-groups of 64
    const int wn   = warp >> 1;           // 4 col-groups of 32
    const int gq   = lane >> 2;           // groupID
    const int tq   = lane & 3;            // threadID_in_group

    const int m0 = ((blockIdx.y >> lg) * TT) + t0 +
                   ((blockIdx.y & ((1 << lg) - 1)) * 128);
    const int n0 = blockIdx.x * 128;

    // stage mapping: thread -> one float4 of A and one of W per chunk
    const int srow = tid >> 1;
    const int skk  = (tid & 1) * 4;

    float acc[4][4][4];
#pragma unroll
    for (int i = 0; i < 4; i++)
#pragma unroll
        for (int j = 0; j < 4; j++)
#pragma unroll
            for (int q = 0; q < 4; q++) acc[i][j][q] = 0.f;

    // bias per thread: cols used in epilogue
    float bias[4][2];
#pragma unroll
    for (int nt = 0; nt < 4; nt++) {
        int col = n0 + wn * 32 + nt * 8 + tq * 2;
        bias[nt][0] = bih[col] + bhh[col];
        bias[nt][1] = bih[col + 1] + bhh[col + 1];
    }

    // stage chunk 0 into buf 0
    {
        float4 av = *(const float4*)(A + (size_t)(m0 + srow) * K + skk);
        float4 bv = *(const float4*)(W + (size_t)(n0 + srow) * K + skk);
        const float aa[4] = {av.x, av.y, av.z, av.w};
        const float bb[4] = {bv.x, bv.y, bv.z, bv.w};
#pragma unroll
        for (int j = 0; j < 4; j++) {
            uint32_t h = f2tf32(aa[j]);
            Ahi[0][srow][skk + j] = __uint_as_float(h);
            Alo[0][srow][skk + j] = aa[j] - __uint_as_float(h);
            h = f2tf32(bb[j]);
            Bhi[0][srow][skk + j] = __uint_as_float(h);
            Blo[0][srow][skk + j] = bb[j] - __uint_as_float(h);
        }
    }
    __syncthreads();

    const int NC = K / 8;
    for (int c = 0; c < NC; ++c) {
        const int cur = c & 1, nxt = cur ^ 1;
        float aa[4], bb[4];
        if (c + 1 < NC) {
            float4 av = *(const float4*)(A + (size_t)(m0 + srow) * K + (c + 1) * 8 + skk);
            float4 bv = *(const float4*)(W + (size_t)(n0 + srow) * K + (c + 1) * 8 + skk);
            aa[0] = av.x; aa[1] = av.y; aa[2] = av.z; aa[3] = av.w;
            bb[0] = bv.x; bb[1] = bv.y; bb[2] = bv.z; bb[3] = bv.w;
        }

        // preload B fragments for all 4 n-tiles
        uint32_t bh[4][2], bl[4][2];
#pragma unroll
        for (int nt = 0; nt < 4; nt++) {
            int nr = wn * 32 + nt * 8 + gq;
            bh[nt][0] = __float_as_uint(Bhi[cur][nr][tq]);
            bh[nt][1] = __float_as_uint(Bhi[cur][nr][tq + 4]);
            bl[nt][0] = __float_as_uint(Blo[cur][nr][tq]);
            bl[nt][1] = __float_as_uint(Blo[cur][nr][tq + 4]);
        }
#pragma unroll
        for (int mt = 0; mt < 4; mt++) {
            int mr = wm * 64 + mt * 16 + gq;
            uint32_t ah0 = __float_as_uint(Ahi[cur][mr][tq]);
            uint32_t ah1 = __float_as_uint(Ahi[cur][mr + 8][tq]);
            uint32_t ah2 = __float_as_uint(Ahi[cur][mr][tq + 4]);
            uint32_t ah3 = __float_as_uint(Ahi[cur][mr + 8][tq + 4]);
            uint32_t al0 = __float_as_uint(Alo[cur][mr][tq]);
            uint32_t al1 = __float_as_uint(Alo[cur][mr + 8][tq]);
            uint32_t al2 = __float_as_uint(Alo[cur][mr][tq + 4]);
            uint32_t al3 = __float_as_uint(Alo[cur][mr + 8][tq + 4]);
#pragma unroll
            for (int nt = 0; nt < 4; nt++) {
                float* cc = acc[mt][nt];
                mma_tf32(cc[0], cc[1], cc[2], cc[3],
                         ah0, ah1, ah2, ah3, bh[nt][0], bh[nt][1]);
                mma_tf32(cc[0], cc[1], cc[2], cc[3],
                         ah0, ah1, ah2, ah3, bl[nt][0], bl[nt][1]);
                mma_tf32(cc[0], cc[1], cc[2], cc[3],
                         al0, al1, al2, al3, bh[nt][0], bh[nt][1]);
            }
        }

        if (c + 1 < NC) {
#pragma unroll
            for (int j = 0; j < 4; j++) {
                uint32_t h = f2tf32(aa[j]);
                Ahi[nxt][srow][skk + j] = __uint_as_float(h);
                Alo[nxt][srow][skk + j] = aa[j] - __uint_as_float(h);
                h = f2tf32(bb[j]);
                Bhi[nxt][srow][skk + j] = __uint_as_float(h);
                Blo[nxt][srow][skk + j] = bb[j] - __uint_as_float(h);
            }
            __syncthreads();
        }
    }

    // epilogue: + bias, float2 stores
#pragma unroll
    for (int mt = 0; mt < 4; mt++) {
        int row0 = m0 + wm * 64 + mt * 16 + gq;
#pragma unroll
        for (int nt = 0; nt < 4; nt++) {
            int col = n0 + wn * 32 + nt * 8 + tq * 2;
            float* cc = acc[mt][nt];
            *(float2*)(g_xg + (size_t)row0 * G4 + col) =
                make_float2(cc[0] + bias[nt][0], cc[1] + bias[nt][1]);
            *(float2*)(g_xg + (size_t)(row0 + 8) * G4 + col) =
                make_float2(cc[2] + bias[nt][0], cc[3] + bias[nt][1]);
        }
    }
}

// ---------------------------------------------------------------------------
// Recurrent chunk (verbatim from R10 — passing). Cluster of 2 CTAs / 4 batch
// rows; rank r owns h-cols [r*64, r*64+64). grid = (64, n_jobs).
// ---------------------------------------------------------------------------
__global__ __launch_bounds__(512, 1) __cluster_dims__(2, 1, 1)
void lstm_rec10(const float* __restrict__ whh0,
                const float* __restrict__ whh1,
                const float* __restrict__ whh2,
                float* __restrict__ hN, float* __restrict__ cN,
                int4 lsel, int4 tsel)
{
    __shared__ __align__(16) float hbuf[2][4][132];
    __shared__ __align__(16) float land[2][4][68];
    __shared__ __align__(16) float pre[2][256][4];
    __shared__ __align__(8)  ULL   bar;

    const int lc = blockIdx.y;
    const int l  = (lc == 0) ? lsel.x : (lc == 1) ? lsel.y : lsel.z;
    const int t0 = (lc == 0) ? tsel.x : (lc == 1) ? tsel.y : tsel.z;
    const float* whh = (l == 0) ? whh0 : (l == 1) ? whh1 : whh2;
    float* hstate = hN + l * BB * HH;
    float* cstate = cN + l * BB * HH;

    const int tid = threadIdx.x;
    const int r   = blockIdx.x & 1;
    const int b0  = (blockIdx.x >> 1) * 4;

    const int kh = tid >> 8;
    const int jp = tid & 255;
    const int g  = jp >> 6;
    const int nn = jp & 63;

    uint32_t bar_addr = smem_u32(&bar);
    uint32_t peer_bar = mapa_u32(bar_addr, (uint32_t)(r ^ 1));

    if (tid == 0) {
        asm volatile("mbarrier.init.shared.b64 [%0], %1;"
                     :: "r"(bar_addr), "r"(8) : "memory");
    }
    {
        int row = tid >> 7, n = tid & 127;
        hbuf[1][row][n] = hstate[(b0 + row) * HH + n];
    }

    const int row_w = g * 128 + r * 64 + nn;
    ULL w2[32];
    const ULL* wp = (const ULL*)(whh + (size_t)row_w * HH + kh * 64);
#pragma unroll
    for (int i = 0; i < 32; i++) w2[i] = wp[i];

    const bool is_gate = (kh == (r ^ 1));
    const int row_g = jp & 3;
    const int nn_g  = jp >> 2;
    const int n_g   = r * 64 + nn_g;

    float c = 0.f, hlast = 0.f;
    const float* px = g_xg + ((size_t)(b0 + row_g) * TT) * G4 + n_g;
    float*       py = g_y  + ((size_t)(b0 + row_g) * TT) * HH + n_g;
    uint32_t pl0 = 0, pl1 = 0;
    float xc0=0,xc1=0,xc2=0,xc3=0, xn0=0,xn1=0,xn2=0,xn3=0;
    if (is_gate) {
        c   = cstate[(b0 + row_g) * HH + n_g];
        pl0 = mapa_u32(smem_u32(&land[0][row_g][nn_g]), (uint32_t)(r ^ 1));
        pl1 = mapa_u32(smem_u32(&land[1][row_g][nn_g]), (uint32_t)(r ^ 1));
        const float* p0 = px + (size_t)t0 * G4;
        xc0 = p0[0];        xc1 = p0[128];        xc2 = p0[256];        xc3 = p0[384];
        xn0 = p0[G4 + 0];   xn1 = p0[G4 + 128];   xn2 = p0[G4 + 256];   xn3 = p0[G4 + 384];
    }

    __syncthreads();
    asm volatile("barrier.cluster.arrive.aligned;" ::: "memory");
    asm volatile("barrier.cluster.wait.aligned;"   ::: "memory");

    for (int s = 0; s < CHUNK; ++s) {
        const int t  = t0 + s;
        const int pr = (s + 1) & 1;
        const int pw = s & 1;

        float s4[4];
#pragma unroll
        for (int rr = 0; rr < 4; rr += 2) {
            ULL a0 = 0, a1 = 0, c0_ = 0, c1_ = 0;
            const ulonglong2* hA = (const ulonglong2*)&hbuf[pr][rr][kh * 64];
            const ulonglong2* hB = (const ulonglong2*)&hbuf[pr][rr + 1][kh * 64];
#pragma unroll
            for (int i = 0; i < 16; i++) {
                ulonglong2 uA = hA[i], uB = hB[i];
                fma2(a0,  w2[2 * i],     uA.x);
                fma2(a1,  w2[2 * i + 1], uA.y);
                fma2(c0_, w2[2 * i],     uB.x);
                fma2(c1_, w2[2 * i + 1], uB.y);
            }
            float x0, x1, x2, x3;
            upk2(a0, x0, x1); upk2(a1, x2, x3);
            s4[rr] = (x0 + x1) + (x2 + x3);
            upk2(c0_, x0, x1); upk2(c1_, x2, x3);
            s4[rr + 1] = (x0 + x1) + (x2 + x3);
        }
        *(float4*)&pre[kh][jp][0] = make_float4(s4[0], s4[1], s4[2], s4[3]);
        __syncthreads();

        if (is_gate) {
            float pi = pre[0][      nn_g][row_g] + pre[1][      nn_g][row_g];
            float pf = pre[0][ 64 + nn_g][row_g] + pre[1][ 64 + nn_g][row_g];
            float pg = pre[0][128 + nn_g][row_g] + pre[1][128 + nn_g][row_g];
            float po = pre[0][192 + nn_g][row_g] + pre[1][192 + nn_g][row_g];
            float iv = sigapx(pi + xc0);
            float fv = sigapx(pf + xc1);
            float gv = tanhapx(pg + xc2);
            float ov = sigapx(po + xc3);
            c = fv * c + iv * gv;
            float hh = ov * tanhapx(c);
            hlast = hh;
            uint32_t pa = pw ? pl1 : pl0;
            asm volatile("st.shared::cluster.f32 [%0], %1;"
                         :: "r"(pa), "f"(hh) : "memory");
            hbuf[pw][row_g][n_g] = hh;
            __syncwarp();
            if ((tid & 31) == 0) {
                asm volatile("mbarrier.arrive.release.cluster.shared::cluster.b64 _, [%0];"
                             :: "r"(peer_bar) : "memory");
            }
            {
                unsigned par = (unsigned)(s & 1);
                asm volatile(
                    "{\n\t"
                    ".reg .pred P1;\n\t"
                    "WLP%=:\n\t"
                    "mbarrier.try_wait.parity.acquire.cluster.shared::cta.b64 P1, [%0], %1, 0x989680;\n\t"
                    "@!P1 bra WLP%=;\n\t"
                    "}"
                    :: "r"(bar_addr), "r"(par) : "memory");
            }
            hbuf[pw][row_g][((r ^ 1) * 64) + nn_g] = land[pw][row_g][nn_g];
        }
        __syncthreads();

        if (is_gate) {
            py[(size_t)t * HH] = hlast;
            float xf0 = 0, xf1 = 0, xf2 = 0, xf3 = 0;
            if (s + 2 < CHUNK) {
                const float* p2 = px + (size_t)(t + 2) * G4;
                xf0 = p2[0]; xf1 = p2[128]; xf2 = p2[256]; xf3 = p2[384];
            }
            xc0 = xn0; xc1 = xn1; xc2 = xn2; xc3 = xn3;
            xn0 = xf0; xn1 = xf1; xn2 = xf2; xn3 = xf3;
        }
    }

    if (is_gate) {
        hstate[(b0 + row_g) * HH + n_g] = hlast;
        cstate[(b0 + row_g) * HH + n_g] = c;
    }
    asm volatile("barrier.cluster.arrive.aligned;" ::: "memory");
    asm volatile("barrier.cluster.wait.aligned;"   ::: "memory");
}

// ---------------------------------------------------------------------------
// Output projection: out[bt] = relu(y3[bt,:] . Wout + bout), one warp per row
// ---------------------------------------------------------------------------
__global__ __launch_bounds__(256)
void proj_kernel(const float* __restrict__ wout,
                 const float* __restrict__ bout,
                 float* __restrict__ out)
{
    int gwarp = (blockIdx.x * blockDim.x + threadIdx.x) >> 5;
    int lane  = threadIdx.x & 31;
    if (gwarp >= MROWS) return;
    float4 yv = ((const float4*)(g_y + (size_t)gwarp * HH))[lane];
    float4 wv = ((const float4*)wout)[lane];
    float s = yv.x * wv.x + yv.y * wv.y + yv.z * wv.z + yv.w * wv.w;
#pragma unroll
    for (int o = 16; o; o >>= 1) s += __shfl_xor_sync(0xFFFFFFFFu, s, o);
    if (lane == 0) out[gwarp] = fmaxf(s + bout[0], 0.f);
}

// ---------------------------------------------------------------------------
// Schedule (NCHUNK=2): waves never exceed 128 CTAs.
//   gemm l0 (full T)
//   w0: rec(l0,c0)
//   gemm(l1,c0)
//   w1: rec(l0,c1) + rec(l1,c0)
//   gemm(l1,c1), gemm(l2,c0)
//   w2: rec(l1,c1) + rec(l2,c0)
//   gemm(l2,c1)
//   w3: rec(l2,c1)
//   proj
// ---------------------------------------------------------------------------
extern "C" void kernel_launch(void* const* d_in, const int* in_sizes, int n_in,
                              void* d_out, int out_size)
{
    const float* x    = (const float*)d_in[0];
    const float* h0   = (const float*)d_in[1];
    const float* c0   = (const float*)d_in[2];
    const float* Wih[3] = {(const float*)d_in[3], (const float*)d_in[7],  (const float*)d_in[11]};
    const float* Whh[3] = {(const float*)d_in[4], (const float*)d_in[8],  (const float*)d_in[12]};
    const float* bih[3] = {(const float*)d_in[5], (const float*)d_in[9],  (const float*)d_in[13]};
    const float* bhh[3] = {(const float*)d_in[6], (const float*)d_in[10], (const float*)d_in[14]};
    const float* Wout = (const float*)d_in[15];
    const float* bout = (const float*)d_in[16];

    float* out = (float*)d_out;           // [B*T]
    float* hN  = out + MROWS;             // [3,B,H] = live state + final output
    float* cN  = hN + 3 * BB * HH;

    init_state<<<(3 * BB * HH + 511) / 512, 512>>>(h0, c0, hN, cN);

    // layer-0 xg, full T: grid (4, 128*8), lg=3 (8 tiles of 128 per batch row)
    xg_tf32<64><<<dim3(4, 1024), 256>>>(x, 0, Wih[0], bih[0], bhh[0], 0, 3);

    // wave 0: rec(l0, c0)
    lstm_rec10<<<dim3(64, 1), 512>>>(Whh[0], Whh[1], Whh[2], hN, cN,
                                     make_int4(0, 0, 0, 0),
                                     make_int4(0, 0, 0, 0));
    // gemm(l1, c0): grid (4, 128*4), lg=2
    xg_tf32<128><<<dim3(4, 512), 256>>>(nullptr, 1, Wih[1], bih[1], bhh[1], 0, 2);

    // wave 1: rec(l0, c1) + rec(l1, c0)
    lstm_rec10<<<dim3(64, 2), 512>>>(Whh[0], Whh[1], Whh[2], hN, cN,
                                     make_int4(0, 1, 0, 0),
                                     make_int4(CHUNK, 0, 0, 0));
    xg_tf32<128><<<dim3(4, 512), 256>>>(nullptr, 1, Wih[1], bih[1], bhh[1], CHUNK, 2);
    xg_tf32<128><<<dim3(4, 512), 256>>>(nullptr, 1, Wih[2], bih[2], bhh[2], 0, 2);

    // wave 2: rec(l1, c1) + rec(l2, c0)
    lstm_rec10<<<dim3(64, 2), 512>>>(Whh[0], Whh[1], Whh[2], hN, cN,
                                     make_int4(1, 2, 0, 0),
                                     make_int4(CHUNK, 0, 0, 0));
    xg_tf32<128><<<dim3(4, 512), 256>>>(nullptr, 1, Wih[2], bih[2], bhh[2], CHUNK, 2);

    // wave 3: rec(l2, c1)
    lstm_rec10<<<dim3(64, 1), 512>>>(Whh[0], Whh[1], Whh[2], hN, cN,
                                     make_int4(2, 0, 0, 0),
                                     make_int4(CHUNK, 0, 0, 0));

    proj_kernel<<<MROWS / 8, 256>>>(Wout, bout, out);
}

// round 12
// speedup vs baseline: 1.3304x; 1.0515x over previous
#include <cuda_runtime.h>
#include <cstdint>

typedef unsigned long long ULL;

// Problem constants: B=128, T=1024, H=128, D=64, L=3
#define BB   128
#define TT   1024
#define HH   128
#define G4   512
#define MROWS (BB*TT)
#define CHUNK 256
#define NCHUNK 4

// Scratch (device globals: allocation-rule-safe)
__device__ float g_xg[(size_t)MROWS * G4];   // 256 MB (recycled per layer-chunk)
__device__ float g_y [(size_t)MROWS * HH];   // 64 MB  (recycled per layer-chunk)

// ---------------------------------------------------------------------------
// helpers
// ---------------------------------------------------------------------------
__device__ __forceinline__ void fma2(ULL& acc, ULL a, ULL b) {
    asm("fma.rn.f32x2 %0, %1, %2, %0;" : "+l"(acc) : "l"(a), "l"(b));
}
__device__ __forceinline__ void upk2(ULL v, float& lo, float& hi) {
    asm("mov.b64 {%0, %1}, %2;" : "=f"(lo), "=f"(hi) : "l"(v));
}
__device__ __forceinline__ float tanhapx(float x) {
    float y; asm("tanh.approx.f32 %0, %1;" : "=f"(y) : "f"(x)); return y;
}
__device__ __forceinline__ float sigapx(float x) {
    return fmaf(tanhapx(0.5f * x), 0.5f, 0.5f);
}
__device__ __forceinline__ uint32_t smem_u32(const void* p) {
    uint32_t a;
    asm("{ .reg .u64 t; cvta.to.shared.u64 t, %1; cvt.u32.u64 %0, t; }"
        : "=r"(a) : "l"(p));
    return a;
}
__device__ __forceinline__ uint32_t mapa_u32(uint32_t a, uint32_t rank) {
    uint32_t r;
    asm("mapa.shared::cluster.u32 %0, %1, %2;" : "=r"(r) : "r"(a), "r"(rank));
    return r;
}
__device__ __forceinline__ uint32_t f2tf32(float v) {
    uint32_t r; asm("cvt.rna.tf32.f32 %0, %1;" : "=r"(r) : "f"(v)); return r;
}
__device__ __forceinline__ void mma_tf32(float& c0, float& c1, float& c2, float& c3,
                                         uint32_t a0, uint32_t a1, uint32_t a2, uint32_t a3,
                                         uint32_t b0, uint32_t b1) {
    asm("mma.sync.aligned.m16n8k8.row.col.f32.tf32.tf32.f32 "
        "{%0,%1,%2,%3},{%4,%5,%6,%7},{%8,%9},{%0,%1,%2,%3};"
        : "+f"(c0), "+f"(c1), "+f"(c2), "+f"(c3)
        : "r"(a0), "r"(a1), "r"(a2), "r"(a3), "r"(b0), "r"(b1));
}

// ---------------------------------------------------------------------------
// init: copy h0,c0 -> state arrays (hN, cN in d_out region)
// ---------------------------------------------------------------------------
__global__ void init_state(const float* __restrict__ h0,
                           const float* __restrict__ c0,
                           float* __restrict__ hN, float* __restrict__ cN)
{
    int i = blockIdx.x * blockDim.x + threadIdx.x;
    if (i < 3 * BB * HH) { hN[i] = h0[i]; cN[i] = c0[i]; }
}

// ---------------------------------------------------------------------------
// 3xTF32 tensor-core GEMM, hi/lo INTERLEAVED smem (float2 fragment loads).
// g_xg[m,:] = A[m,:K] @ W[512,K]^T + (bih+bhh)
// BM=BN=128, BK=8, 256 threads (8 warps as 2x4 of 64x32 warp tiles).
// m0 = (by>>lg)*TT + t0 + (by & ((1<<lg)-1))*128 ; n0 = bx*128.
// ---------------------------------------------------------------------------
template<int K>
__global__ __launch_bounds__(256, 2)
void xg_tf32(const float* __restrict__ Aext, int use_gy,
             const float* __restrict__ W,
             const float* __restrict__ bih,
             const float* __restrict__ bhh,
             int t0, int lg)
{
    __shared__ float Ahl[2][128][9][2];   // [buf][row][k(pad9)][hi|lo]
    __shared__ float Bhl[2][128][9][2];

    const float* A = use_gy ? (const float*)g_y : Aext;

    const int tid  = threadIdx.x;
    const int lane = tid & 31;
    const int warp = tid >> 5;
    const int wm   = warp & 1;            // 2 row-groups of 64
    const int wn   = warp >> 1;           // 4 col-groups of 32
    const int gq   = lane >> 2;           // groupID
    const int tq   = lane & 3;            // threadID_in_group

    const int m0 = ((blockIdx.y >> lg) * TT) + t0 +
                   ((blockIdx.y & ((1 << lg) - 1)) * 128);
    const int n0 = blockIdx.x * 128;

    const int srow = tid >> 1;
    const int skk  = (tid & 1) * 4;

    float acc[4][4][4];
#pragma unroll
    for (int i = 0; i < 4; i++)
#pragma unroll
        for (int j = 0; j < 4; j++)
#pragma unroll
            for (int q = 0; q < 4; q++) acc[i][j][q] = 0.f;

    float bias[4][2];
#pragma unroll
    for (int nt = 0; nt < 4; nt++) {
        int col = n0 + wn * 32 + nt * 8 + tq * 2;
        bias[nt][0] = bih[col] + bhh[col];
        bias[nt][1] = bih[col + 1] + bhh[col + 1];
    }

    // stage chunk 0 into buf 0
    {
        float4 av = *(const float4*)(A + (size_t)(m0 + srow) * K + skk);
        float4 bv = *(const float4*)(W + (size_t)(n0 + srow) * K + skk);
        const float aa[4] = {av.x, av.y, av.z, av.w};
        const float bb[4] = {bv.x, bv.y, bv.z, bv.w};
#pragma unroll
        for (int j = 0; j < 4; j++) {
            float h = __uint_as_float(f2tf32(aa[j]));
            *(float2*)&Ahl[0][srow][skk + j][0] = make_float2(h, aa[j] - h);
            h = __uint_as_float(f2tf32(bb[j]));
            *(float2*)&Bhl[0][srow][skk + j][0] = make_float2(h, bb[j] - h);
        }
    }
    __syncthreads();

    const int NC = K / 8;
    for (int c = 0; c < NC; ++c) {
        const int cur = c & 1, nxt = cur ^ 1;
        float aa[4], bb[4];
        if (c + 1 < NC) {
            float4 av = *(const float4*)(A + (size_t)(m0 + srow) * K + (c + 1) * 8 + skk);
            float4 bv = *(const float4*)(W + (size_t)(n0 + srow) * K + (c + 1) * 8 + skk);
            aa[0] = av.x; aa[1] = av.y; aa[2] = av.z; aa[3] = av.w;
            bb[0] = bv.x; bb[1] = bv.y; bb[2] = bv.z; bb[3] = bv.w;
        }

        // preload B fragments for all 4 n-tiles (hi,lo in one LDS.64 each)
        uint32_t bh[4][2], bl[4][2];
#pragma unroll
        for (int nt = 0; nt < 4; nt++) {
            int nr = wn * 32 + nt * 8 + gq;
            float2 v0 = *(const float2*)&Bhl[cur][nr][tq][0];
            float2 v1 = *(const float2*)&Bhl[cur][nr][tq + 4][0];
            bh[nt][0] = __float_as_uint(v0.x); bl[nt][0] = __float_as_uint(v0.y);
            bh[nt][1] = __float_as_uint(v1.x); bl[nt][1] = __float_as_uint(v1.y);
        }
#pragma unroll
        for (int mt = 0; mt < 4; mt++) {
            int mr = wm * 64 + mt * 16 + gq;
            float2 u0 = *(const float2*)&Ahl[cur][mr][tq][0];
            float2 u1 = *(const float2*)&Ahl[cur][mr + 8][tq][0];
            float2 u2 = *(const float2*)&Ahl[cur][mr][tq + 4][0];
            float2 u3 = *(const float2*)&Ahl[cur][mr + 8][tq + 4][0];
            uint32_t ah0 = __float_as_uint(u0.x), al0 = __float_as_uint(u0.y);
            uint32_t ah1 = __float_as_uint(u1.x), al1 = __float_as_uint(u1.y);
            uint32_t ah2 = __float_as_uint(u2.x), al2 = __float_as_uint(u2.y);
            uint32_t ah3 = __float_as_uint(u3.x), al3 = __float_as_uint(u3.y);
#pragma unroll
            for (int nt = 0; nt < 4; nt++) {
                float* cc = acc[mt][nt];
                mma_tf32(cc[0], cc[1], cc[2], cc[3],
                         ah0, ah1, ah2, ah3, bh[nt][0], bh[nt][1]);
                mma_tf32(cc[0], cc[1], cc[2], cc[3],
                         ah0, ah1, ah2, ah3, bl[nt][0], bl[nt][1]);
                mma_tf32(cc[0], cc[1], cc[2], cc[3],
                         al0, al1, al2, al3, bh[nt][0], bh[nt][1]);
            }
        }

        if (c + 1 < NC) {
#pragma unroll
            for (int j = 0; j < 4; j++) {
                float h = __uint_as_float(f2tf32(aa[j]));
                *(float2*)&Ahl[nxt][srow][skk + j][0] = make_float2(h, aa[j] - h);
                h = __uint_as_float(f2tf32(bb[j]));
                *(float2*)&Bhl[nxt][srow][skk + j][0] = make_float2(h, bb[j] - h);
            }
            __syncthreads();
        }
    }

    // epilogue: + bias, float2 stores
#pragma unroll
    for (int mt = 0; mt < 4; mt++) {
        int row0 = m0 + wm * 64 + mt * 16 + gq;
#pragma unroll
        for (int nt = 0; nt < 4; nt++) {
            int col = n0 + wn * 32 + nt * 8 + tq * 2;
            float* cc = acc[mt][nt];
            *(float2*)(g_xg + (size_t)row0 * G4 + col) =
                make_float2(cc[0] + bias[nt][0], cc[1] + bias[nt][1]);
            *(float2*)(g_xg + (size_t)(row0 + 8) * G4 + col) =
                make_float2(cc[2] + bias[nt][0], cc[3] + bias[nt][1]);
        }
    }
}

// ---------------------------------------------------------------------------
// Recurrent chunk (verbatim from R10/R11 — passing; CHUNK now 256).
// Cluster of 2 CTAs / 4 batch rows; rank r owns h-cols [r*64, r*64+64).
// grid = (64, n_jobs).
// ---------------------------------------------------------------------------
__global__ __launch_bounds__(512, 1) __cluster_dims__(2, 1, 1)
void lstm_rec10(const float* __restrict__ whh0,
                const float* __restrict__ whh1,
                const float* __restrict__ whh2,
                float* __restrict__ hN, float* __restrict__ cN,
                int4 lsel, int4 tsel)
{
    __shared__ __align__(16) float hbuf[2][4][132];
    __shared__ __align__(16) float land[2][4][68];
    __shared__ __align__(16) float pre[2][256][4];
    __shared__ __align__(8)  ULL   bar;

    const int lc = blockIdx.y;
    const int l  = (lc == 0) ? lsel.x : (lc == 1) ? lsel.y : lsel.z;
    const int t0 = (lc == 0) ? tsel.x : (lc == 1) ? tsel.y : tsel.z;
    const float* whh = (l == 0) ? whh0 : (l == 1) ? whh1 : whh2;
    float* hstate = hN + l * BB * HH;
    float* cstate = cN + l * BB * HH;

    const int tid = threadIdx.x;
    const int r   = blockIdx.x & 1;
    const int b0  = (blockIdx.x >> 1) * 4;

    const int kh = tid >> 8;
    const int jp = tid & 255;
    const int g  = jp >> 6;
    const int nn = jp & 63;

    uint32_t bar_addr = smem_u32(&bar);
    uint32_t peer_bar = mapa_u32(bar_addr, (uint32_t)(r ^ 1));

    if (tid == 0) {
        asm volatile("mbarrier.init.shared.b64 [%0], %1;"
                     :: "r"(bar_addr), "r"(8) : "memory");
    }
    {
        int row = tid >> 7, n = tid & 127;
        hbuf[1][row][n] = hstate[(b0 + row) * HH + n];
    }

    const int row_w = g * 128 + r * 64 + nn;
    ULL w2[32];
    const ULL* wp = (const ULL*)(whh + (size_t)row_w * HH + kh * 64);
#pragma unroll
    for (int i = 0; i < 32; i++) w2[i] = wp[i];

    const bool is_gate = (kh == (r ^ 1));
    const int row_g = jp & 3;
    const int nn_g  = jp >> 2;
    const int n_g   = r * 64 + nn_g;

    float c = 0.f, hlast = 0.f;
    const float* px = g_xg + ((size_t)(b0 + row_g) * TT) * G4 + n_g;
    float*       py = g_y  + ((size_t)(b0 + row_g) * TT) * HH + n_g;
    uint32_t pl0 = 0, pl1 = 0;
    float xc0=0,xc1=0,xc2=0,xc3=0, xn0=0,xn1=0,xn2=0,xn3=0;
    if (is_gate) {
        c   = cstate[(b0 + row_g) * HH + n_g];
        pl0 = mapa_u32(smem_u32(&land[0][row_g][nn_g]), (uint32_t)(r ^ 1));
        pl1 = mapa_u32(smem_u32(&land[1][row_g][nn_g]), (uint32_t)(r ^ 1));
        const float* p0 = px + (size_t)t0 * G4;
        xc0 = p0[0];        xc1 = p0[128];        xc2 = p0[256];        xc3 = p0[384];
        xn0 = p0[G4 + 0];   xn1 = p0[G4 + 128];   xn2 = p0[G4 + 256];   xn3 = p0[G4 + 384];
    }

    __syncthreads();
    asm volatile("barrier.cluster.arrive.aligned;" ::: "memory");
    asm volatile("barrier.cluster.wait.aligned;"   ::: "memory");

    for (int s = 0; s < CHUNK; ++s) {
        const int t  = t0 + s;
        const int pr = (s + 1) & 1;
        const int pw = s & 1;

        float s4[4];
#pragma unroll
        for (int rr = 0; rr < 4; rr += 2) {
            ULL a0 = 0, a1 = 0, c0_ = 0, c1_ = 0;
            const ulonglong2* hA = (const ulonglong2*)&hbuf[pr][rr][kh * 64];
            const ulonglong2* hB = (const ulonglong2*)&hbuf[pr][rr + 1][kh * 64];
#pragma unroll
            for (int i = 0; i < 16; i++) {
                ulonglong2 uA = hA[i], uB = hB[i];
                fma2(a0,  w2[2 * i],     uA.x);
                fma2(a1,  w2[2 * i + 1], uA.y);
                fma2(c0_, w2[2 * i],     uB.x);
                fma2(c1_, w2[2 * i + 1], uB.y);
            }
            float x0, x1, x2, x3;
            upk2(a0, x0, x1); upk2(a1, x2, x3);
            s4[rr] = (x0 + x1) + (x2 + x3);
            upk2(c0_, x0, x1); upk2(c1_, x2, x3);
            s4[rr + 1] = (x0 + x1) + (x2 + x3);
        }
        *(float4*)&pre[kh][jp][0] = make_float4(s4[0], s4[1], s4[2], s4[3]);
        __syncthreads();

        if (is_gate) {
            float pi = pre[0][      nn_g][row_g] + pre[1][      nn_g][row_g];
            float pf = pre[0][ 64 + nn_g][row_g] + pre[1][ 64 + nn_g][row_g];
            float pg = pre[0][128 + nn_g][row_g] + pre[1][128 + nn_g][row_g];
            float po = pre[0][192 + nn_g][row_g] + pre[1][192 + nn_g][row_g];
            float iv = sigapx(pi + xc0);
            float fv = sigapx(pf + xc1);
            float gv = tanhapx(pg + xc2);
            float ov = sigapx(po + xc3);
            c = fv * c + iv * gv;
            float hh = ov * tanhapx(c);
            hlast = hh;
            uint32_t pa = pw ? pl1 : pl0;
            asm volatile("st.shared::cluster.f32 [%0], %1;"
                         :: "r"(pa), "f"(hh) : "memory");
            hbuf[pw][row_g][n_g] = hh;
            __syncwarp();
            if ((tid & 31) == 0) {
                asm volatile("mbarrier.arrive.release.cluster.shared::cluster.b64 _, [%0];"
                             :: "r"(peer_bar) : "memory");
            }
            {
                unsigned par = (unsigned)(s & 1);
                asm volatile(
                    "{\n\t"
                    ".reg .pred P1;\n\t"
                    "WLP%=:\n\t"
                    "mbarrier.try_wait.parity.acquire.cluster.shared::cta.b64 P1, [%0], %1, 0x989680;\n\t"
                    "@!P1 bra WLP%=;\n\t"
                    "}"
                    :: "r"(bar_addr), "r"(par) : "memory");
            }
            hbuf[pw][row_g][((r ^ 1) * 64) + nn_g] = land[pw][row_g][nn_g];
        }
        __syncthreads();

        if (is_gate) {
            py[(size_t)t * HH] = hlast;
            float xf0 = 0, xf1 = 0, xf2 = 0, xf3 = 0;
            if (s + 2 < CHUNK) {
                const float* p2 = px + (size_t)(t + 2) * G4;
                xf0 = p2[0]; xf1 = p2[128]; xf2 = p2[256]; xf3 = p2[384];
            }
            xc0 = xn0; xc1 = xn1; xc2 = xn2; xc3 = xn3;
            xn0 = xf0; xn1 = xf1; xn2 = xf2; xn3 = xf3;
        }
    }

    if (is_gate) {
        hstate[(b0 + row_g) * HH + n_g] = hlast;
        cstate[(b0 + row_g) * HH + n_g] = c;
    }
    asm volatile("barrier.cluster.arrive.aligned;" ::: "memory");
    asm volatile("barrier.cluster.wait.aligned;"   ::: "memory");
}

// ---------------------------------------------------------------------------
// Output projection: out[bt] = relu(y3[bt,:] . Wout + bout), one warp per row
// ---------------------------------------------------------------------------
__global__ __launch_bounds__(256)
void proj_kernel(const float* __restrict__ wout,
                 const float* __restrict__ bout,
                 float* __restrict__ out)
{
    int gwarp = (blockIdx.x * blockDim.x + threadIdx.x) >> 5;
    int lane  = threadIdx.x & 31;
    if (gwarp >= MROWS) return;
    float4 yv = ((const float4*)(g_y + (size_t)gwarp * HH))[lane];
    float4 wv = ((const float4*)wout)[lane];
    float s = yv.x * wv.x + yv.y * wv.y + yv.z * wv.z + yv.w * wv.w;
#pragma unroll
    for (int o = 16; o; o >>= 1) s += __shfl_xor_sync(0xFFFFFFFFu, s, o);
    if (lane == 0) out[gwarp] = fmaxf(s + bout[0], 0.f);
}

// ---------------------------------------------------------------------------
// Schedule (NCHUNK=4, 7 walls, <=2 jobs/wall, all hazards audited):
//  gemmL0(all) | w0:l0c0 | g(l1c0) | w1:l0c1,l1c0 | g(l1c1),g(l2c0) |
//  w2:l0c2,l1c1 | g(l1c2),g(l2c1) | w3:l0c3,l2c0 | g(l1c3) |
//  w4:l1c2,l2c1 | g(l2c2) | w5:l1c3,l2c2 | g(l2c3) | w6:l2c3 | proj
// ---------------------------------------------------------------------------
extern "C" void kernel_launch(void* const* d_in, const int* in_sizes, int n_in,
                              void* d_out, int out_size)
{
    const float* x    = (const float*)d_in[0];
    const float* h0   = (const float*)d_in[1];
    const float* c0   = (const float*)d_in[2];
    const float* Wih[3] = {(const float*)d_in[3], (const float*)d_in[7],  (const float*)d_in[11]};
    const float* Whh[3] = {(const float*)d_in[4], (const float*)d_in[8],  (const float*)d_in[12]};
    const float* bih[3] = {(const float*)d_in[5], (const float*)d_in[9],  (const float*)d_in[13]};
    const float* bhh[3] = {(const float*)d_in[6], (const float*)d_in[10], (const float*)d_in[14]};
    const float* Wout = (const float*)d_in[15];
    const float* bout = (const float*)d_in[16];

    float* out = (float*)d_out;           // [B*T]
    float* hN  = out + MROWS;             // [3,B,H] = live state + final output
    float* cN  = hN + 3 * BB * HH;

    init_state<<<(3 * BB * HH + 511) / 512, 512>>>(h0, c0, hN, cN);

    // layer-0 xg, full T: grid (4, 1024), lg=3
    xg_tf32<64><<<dim3(4, 1024), 256>>>(x, 0, Wih[0], bih[0], bhh[0], 0, 3);

    const int C = CHUNK;
    auto rec1 = [&](int l0_, int t0_) {
        lstm_rec10<<<dim3(64, 1), 512>>>(Whh[0], Whh[1], Whh[2], hN, cN,
                                         make_int4(l0_, 0, 0, 0),
                                         make_int4(t0_, 0, 0, 0));
    };
    auto rec2 = [&](int la, int ta, int lb, int tb) {
        lstm_rec10<<<dim3(64, 2), 512>>>(Whh[0], Whh[1], Whh[2], hN, cN,
                                         make_int4(la, lb, 0, 0),
                                         make_int4(ta, tb, 0, 0));
    };
    auto gemm = [&](int l, int t0_) {
        xg_tf32<128><<<dim3(4, 256), 256>>>(nullptr, 1, Wih[l], bih[l], bhh[l],
                                            t0_, 1);
    };

    rec1(0, 0);                               // w0: l0c0
    gemm(1, 0);
    rec2(0, 1 * C, 1, 0);                     // w1: l0c1, l1c0
    gemm(1, 1 * C); gemm(2, 0);
    rec2(0, 2 * C, 1, 1 * C);                 // w2: l0c2, l1c1
    gemm(1, 2 * C); gemm(2, 1 * C);
    rec2(0, 3 * C, 2, 0);                     // w3: l0c3, l2c0
    gemm(1, 3 * C);
    rec2(1, 2 * C, 2, 1 * C);                 // w4: l1c2, l2c1
    gemm(2, 2 * C);
    rec2(1, 3 * C, 2, 2 * C);                 // w5: l1c3, l2c2
    gemm(2, 3 * C);
    rec1(2, 3 * C);                           // w6: l2c3

    proj_kernel<<<MROWS / 8, 256>>>(Wout, bout, out);
}

// round 13
// speedup vs baseline: 1.3356x; 1.0039x over previous
#include <cuda_runtime.h>
#include <cstdint>

typedef unsigned long long ULL;

// Problem constants: B=128, T=1024, H=128, D=64, L=3
#define BB   128
#define TT   1024
#define HH   128
#define G4   512
#define MROWS (BB*TT)
#define CHUNK 128
#define NCHUNK 8

// Scratch (device globals: allocation-rule-safe)
__device__ float g_xg[(size_t)MROWS * G4];    // 256 MB (recycled per layer-chunk)
__device__ float g_y [(size_t)MROWS * HH];    // 64 MB  (recycled per layer-chunk)
__device__ float g_whl[3][512 * 128 * 2];     // per-layer Wih as interleaved (hi,lo)

// ---------------------------------------------------------------------------
// helpers
// ---------------------------------------------------------------------------
__device__ __forceinline__ void fma2(ULL& acc, ULL a, ULL b) {
    asm("fma.rn.f32x2 %0, %1, %2, %0;" : "+l"(acc) : "l"(a), "l"(b));
}
__device__ __forceinline__ void upk2(ULL v, float& lo, float& hi) {
    asm("mov.b64 {%0, %1}, %2;" : "=f"(lo), "=f"(hi) : "l"(v));
}
__device__ __forceinline__ float tanhapx(float x) {
    float y; asm("tanh.approx.f32 %0, %1;" : "=f"(y) : "f"(x)); return y;
}
__device__ __forceinline__ float sigapx(float x) {
    return fmaf(tanhapx(0.5f * x), 0.5f, 0.5f);
}
__device__ __forceinline__ uint32_t smem_u32(const void* p) {
    uint32_t a;
    asm("{ .reg .u64 t; cvta.to.shared.u64 t, %1; cvt.u32.u64 %0, t; }"
        : "=r"(a) : "l"(p));
    return a;
}
__device__ __forceinline__ uint32_t mapa_u32(uint32_t a, uint32_t rank) {
    uint32_t r;
    asm("mapa.shared::cluster.u32 %0, %1, %2;" : "=r"(r) : "r"(a), "r"(rank));
    return r;
}
__device__ __forceinline__ uint32_t f2tf32(float v) {
    uint32_t r; asm("cvt.rna.tf32.f32 %0, %1;" : "=r"(r) : "f"(v)); return r;
}
__device__ __forceinline__ void mma_tf32(float& c0, float& c1, float& c2, float& c3,
                                         uint32_t a0, uint32_t a1, uint32_t a2, uint32_t a3,
                                         uint32_t b0, uint32_t b1) {
    asm("mma.sync.aligned.m16n8k8.row.col.f32.tf32.tf32.f32 "
        "{%0,%1,%2,%3},{%4,%5,%6,%7},{%8,%9},{%0,%1,%2,%3};"
        : "+f"(c0), "+f"(c1), "+f"(c2), "+f"(c3)
        : "r"(a0), "r"(a1), "r"(a2), "r"(a3), "r"(b0), "r"(b1));
}

// ---------------------------------------------------------------------------
// init: copy h0,c0 -> state arrays
// ---------------------------------------------------------------------------
__global__ void init_state(const float* __restrict__ h0,
                           const float* __restrict__ c0,
                           float* __restrict__ hN, float* __restrict__ cN)
{
    int i = blockIdx.x * blockDim.x + threadIdx.x;
    if (i < 3 * BB * HH) { hN[i] = h0[i]; cN[i] = c0[i]; }
}

// ---------------------------------------------------------------------------
// w_conv: W[512*K] -> g_whl[l] interleaved (hi, lo)
// ---------------------------------------------------------------------------
__global__ void w_conv(const float* __restrict__ W, int l, int n)
{
    int i = blockIdx.x * blockDim.x + threadIdx.x;
    if (i < n) {
        float v = W[i];
        float h = __uint_as_float(f2tf32(v));
        g_whl[l][2 * i]     = h;
        g_whl[l][2 * i + 1] = v - h;
    }
}

// ---------------------------------------------------------------------------
// 3xTF32 tensor-core GEMM, W pre-converted (pure-copy B staging).
// g_xg[m,:] = A[m,:K] @ W[512,K]^T + (bih+bhh)
// BM=BN=128, BK=8, 256 threads (8 warps as 2x4 of 64x32 warp tiles).
// m0 = (by>>lg)*TT + t0 + (by & ((1<<lg)-1))*128 ; n0 = bx*128.
// ---------------------------------------------------------------------------
template<int K>
__global__ __launch_bounds__(256, 2)
void xg_tf32(const float* __restrict__ Aext, int use_gy, int layer,
             const float* __restrict__ bih,
             const float* __restrict__ bhh,
             int t0, int lg)
{
    __shared__ float Ahl[2][128][9][2];   // [buf][row][k(pad9)][hi|lo]
    __shared__ float Bhl[2][128][9][2];

    const float* A   = use_gy ? (const float*)g_y : Aext;
    const float* Whl = g_whl[layer];

    const int tid  = threadIdx.x;
    const int lane = tid & 31;
    const int warp = tid >> 5;
    const int wm   = warp & 1;
    const int wn   = warp >> 1;
    const int gq   = lane >> 2;
    const int tq   = lane & 3;

    const int m0 = ((blockIdx.y >> lg) * TT) + t0 +
                   ((blockIdx.y & ((1 << lg) - 1)) * 128);
    const int n0 = blockIdx.x * 128;

    const int srow = tid >> 1;
    const int skk  = (tid & 1) * 4;

    float acc[4][4][4];
#pragma unroll
    for (int i = 0; i < 4; i++)
#pragma unroll
        for (int j = 0; j < 4; j++)
#pragma unroll
            for (int q = 0; q < 4; q++) acc[i][j][q] = 0.f;

    float bias[4][2];
#pragma unroll
    for (int nt = 0; nt < 4; nt++) {
        int col = n0 + wn * 32 + nt * 8 + tq * 2;
        bias[nt][0] = bih[col] + bhh[col];
        bias[nt][1] = bih[col + 1] + bhh[col + 1];
    }

    // stage chunk 0 into buf 0
    {
        float4 av = *(const float4*)(A + (size_t)(m0 + srow) * K + skk);
        const float aa[4] = {av.x, av.y, av.z, av.w};
#pragma unroll
        for (int j = 0; j < 4; j++) {
            float h = __uint_as_float(f2tf32(aa[j]));
            *(float2*)&Ahl[0][srow][skk + j][0] = make_float2(h, aa[j] - h);
        }
        const float4* wv = (const float4*)(Whl + ((size_t)(n0 + srow) * K + skk) * 2);
        float4 w0 = wv[0], w1 = wv[1];
        *(float2*)&Bhl[0][srow][skk + 0][0] = make_float2(w0.x, w0.y);
        *(float2*)&Bhl[0][srow][skk + 1][0] = make_float2(w0.z, w0.w);
        *(float2*)&Bhl[0][srow][skk + 2][0] = make_float2(w1.x, w1.y);
        *(float2*)&Bhl[0][srow][skk + 3][0] = make_float2(w1.z, w1.w);
    }
    __syncthreads();

    const int NC = K / 8;
    for (int c = 0; c < NC; ++c) {
        const int cur = c & 1, nxt = cur ^ 1;
        float aa[4];
        float4 w0, w1;
        if (c + 1 < NC) {
            float4 av = *(const float4*)(A + (size_t)(m0 + srow) * K + (c + 1) * 8 + skk);
            aa[0] = av.x; aa[1] = av.y; aa[2] = av.z; aa[3] = av.w;
            const float4* wv = (const float4*)(Whl +
                ((size_t)(n0 + srow) * K + (c + 1) * 8 + skk) * 2);
            w0 = wv[0]; w1 = wv[1];
        }

        uint32_t bh[4][2], bl[4][2];
#pragma unroll
        for (int nt = 0; nt < 4; nt++) {
            int nr = wn * 32 + nt * 8 + gq;
            float2 v0 = *(const float2*)&Bhl[cur][nr][tq][0];
            float2 v1 = *(const float2*)&Bhl[cur][nr][tq + 4][0];
            bh[nt][0] = __float_as_uint(v0.x); bl[nt][0] = __float_as_uint(v0.y);
            bh[nt][1] = __float_as_uint(v1.x); bl[nt][1] = __float_as_uint(v1.y);
        }
#pragma unroll
        for (int mt = 0; mt < 4; mt++) {
            int mr = wm * 64 + mt * 16 + gq;
            float2 u0 = *(const float2*)&Ahl[cur][mr][tq][0];
            float2 u1 = *(const float2*)&Ahl[cur][mr + 8][tq][0];
            float2 u2 = *(const float2*)&Ahl[cur][mr][tq + 4][0];
            float2 u3 = *(const float2*)&Ahl[cur][mr + 8][tq + 4][0];
            uint32_t ah0 = __float_as_uint(u0.x), al0 = __float_as_uint(u0.y);
            uint32_t ah1 = __float_as_uint(u1.x), al1 = __float_as_uint(u1.y);
            uint32_t ah2 = __float_as_uint(u2.x), al2 = __float_as_uint(u2.y);
            uint32_t ah3 = __float_as_uint(u3.x), al3 = __float_as_uint(u3.y);
#pragma unroll
            for (int nt = 0; nt < 4; nt++) {
                float* cc = acc[mt][nt];
                mma_tf32(cc[0], cc[1], cc[2], cc[3],
                         ah0, ah1, ah2, ah3, bh[nt][0], bh[nt][1]);
                mma_tf32(cc[0], cc[1], cc[2], cc[3],
                         ah0, ah1, ah2, ah3, bl[nt][0], bl[nt][1]);
                mma_tf32(cc[0], cc[1], cc[2], cc[3],
                         al0, al1, al2, al3, bh[nt][0], bh[nt][1]);
            }
        }

        if (c + 1 < NC) {
#pragma unroll
            for (int j = 0; j < 4; j++) {
                float h = __uint_as_float(f2tf32(aa[j]));
                *(float2*)&Ahl[nxt][srow][skk + j][0] = make_float2(h, aa[j] - h);
            }
            *(float2*)&Bhl[nxt][srow][skk + 0][0] = make_float2(w0.x, w0.y);
            *(float2*)&Bhl[nxt][srow][skk + 1][0] = make_float2(w0.z, w0.w);
            *(float2*)&Bhl[nxt][srow][skk + 2][0] = make_float2(w1.x, w1.y);
            *(float2*)&Bhl[nxt][srow][skk + 3][0] = make_float2(w1.z, w1.w);
            __syncthreads();
        }
    }

    // epilogue: + bias, float2 stores
#pragma unroll
    for (int mt = 0; mt < 4; mt++) {
        int row0 = m0 + wm * 64 + mt * 16 + gq;
#pragma unroll
        for (int nt = 0; nt < 4; nt++) {
            int col = n0 + wn * 32 + nt * 8 + tq * 2;
            float* cc = acc[mt][nt];
            *(float2*)(g_xg + (size_t)row0 * G4 + col) =
                make_float2(cc[0] + bias[nt][0], cc[1] + bias[nt][1]);
            *(float2*)(g_xg + (size_t)(row0 + 8) * G4 + col) =
                make_float2(cc[2] + bias[nt][0], cc[3] + bias[nt][1]);
        }
    }
}

// ---------------------------------------------------------------------------
// Recurrent chunk (verbatim from R10/R11/R12 — passing; CHUNK now 128).
// Cluster of 2 CTAs / 4 batch rows; rank r owns h-cols [r*64, r*64+64).
// grid = (64, n_jobs).
// ---------------------------------------------------------------------------
__global__ __launch_bounds__(512, 1) __cluster_dims__(2, 1, 1)
void lstm_rec10(const float* __restrict__ whh0,
                const float* __restrict__ whh1,
                const float* __restrict__ whh2,
                float* __restrict__ hN, float* __restrict__ cN,
                int4 lsel, int4 tsel)
{
    __shared__ __align__(16) float hbuf[2][4][132];
    __shared__ __align__(16) float land[2][4][68];
    __shared__ __align__(16) float pre[2][256][4];
    __shared__ __align__(8)  ULL   bar;

    const int lc = blockIdx.y;
    const int l  = (lc == 0) ? lsel.x : (lc == 1) ? lsel.y : lsel.z;
    const int t0 = (lc == 0) ? tsel.x : (lc == 1) ? tsel.y : tsel.z;
    const float* whh = (l == 0) ? whh0 : (l == 1) ? whh1 : whh2;
    float* hstate = hN + l * BB * HH;
    float* cstate = cN + l * BB * HH;

    const int tid = threadIdx.x;
    const int r   = blockIdx.x & 1;
    const int b0  = (blockIdx.x >> 1) * 4;

    const int kh = tid >> 8;
    const int jp = tid & 255;
    const int g  = jp >> 6;
    const int nn = jp & 63;

    uint32_t bar_addr = smem_u32(&bar);
    uint32_t peer_bar = mapa_u32(bar_addr, (uint32_t)(r ^ 1));

    if (tid == 0) {
        asm volatile("mbarrier.init.shared.b64 [%0], %1;"
                     :: "r"(bar_addr), "r"(8) : "memory");
    }
    {
        int row = tid >> 7, n = tid & 127;
        hbuf[1][row][n] = hstate[(b0 + row) * HH + n];
    }

    const int row_w = g * 128 + r * 64 + nn;
    ULL w2[32];
    const ULL* wp = (const ULL*)(whh + (size_t)row_w * HH + kh * 64);
#pragma unroll
    for (int i = 0; i < 32; i++) w2[i] = wp[i];

    const bool is_gate = (kh == (r ^ 1));
    const int row_g = jp & 3;
    const int nn_g  = jp >> 2;
    const int n_g   = r * 64 + nn_g;

    float c = 0.f, hlast = 0.f;
    const float* px = g_xg + ((size_t)(b0 + row_g) * TT) * G4 + n_g;
    float*       py = g_y  + ((size_t)(b0 + row_g) * TT) * HH + n_g;
    uint32_t pl0 = 0, pl1 = 0;
    float xc0=0,xc1=0,xc2=0,xc3=0, xn0=0,xn1=0,xn2=0,xn3=0;
    if (is_gate) {
        c   = cstate[(b0 + row_g) * HH + n_g];
        pl0 = mapa_u32(smem_u32(&land[0][row_g][nn_g]), (uint32_t)(r ^ 1));
        pl1 = mapa_u32(smem_u32(&land[1][row_g][nn_g]), (uint32_t)(r ^ 1));
        const float* p0 = px + (size_t)t0 * G4;
        xc0 = p0[0];        xc1 = p0[128];        xc2 = p0[256];        xc3 = p0[384];
        xn0 = p0[G4 + 0];   xn1 = p0[G4 + 128];   xn2 = p0[G4 + 256];   xn3 = p0[G4 + 384];
    }

    __syncthreads();
    asm volatile("barrier.cluster.arrive.aligned;" ::: "memory");
    asm volatile("barrier.cluster.wait.aligned;"   ::: "memory");

    for (int s = 0; s < CHUNK; ++s) {
        const int t  = t0 + s;
        const int pr = (s + 1) & 1;
        const int pw = s & 1;

        float s4[4];
#pragma unroll
        for (int rr = 0; rr < 4; rr += 2) {
            ULL a0 = 0, a1 = 0, c0_ = 0, c1_ = 0;
            const ulonglong2* hA = (const ulonglong2*)&hbuf[pr][rr][kh * 64];
            const ulonglong2* hB = (const ulonglong2*)&hbuf[pr][rr + 1][kh * 64];
#pragma unroll
            for (int i = 0; i < 16; i++) {
                ulonglong2 uA = hA[i], uB = hB[i];
                fma2(a0,  w2[2 * i],     uA.x);
                fma2(a1,  w2[2 * i + 1], uA.y);
                fma2(c0_, w2[2 * i],     uB.x);
                fma2(c1_, w2[2 * i + 1], uB.y);
            }
            float x0, x1, x2, x3;
            upk2(a0, x0, x1); upk2(a1, x2, x3);
            s4[rr] = (x0 + x1) + (x2 + x3);
            upk2(c0_, x0, x1); upk2(c1_, x2, x3);
            s4[rr + 1] = (x0 + x1) + (x2 + x3);
        }
        *(float4*)&pre[kh][jp][0] = make_float4(s4[0], s4[1], s4[2], s4[3]);
        __syncthreads();

        if (is_gate) {
            float pi = pre[0][      nn_g][row_g] + pre[1][      nn_g][row_g];
            float pf = pre[0][ 64 + nn_g][row_g] + pre[1][ 64 + nn_g][row_g];
            float pg = pre[0][128 + nn_g][row_g] + pre[1][128 + nn_g][row_g];
            float po = pre[0][192 + nn_g][row_g] + pre[1][192 + nn_g][row_g];
            float iv = sigapx(pi + xc0);
            float fv = sigapx(pf + xc1);
            float gv = tanhapx(pg + xc2);
            float ov = sigapx(po + xc3);
            c = fv * c + iv * gv;
            float hh = ov * tanhapx(c);
            hlast = hh;
            uint32_t pa = pw ? pl1 : pl0;
            asm volatile("st.shared::cluster.f32 [%0], %1;"
                         :: "r"(pa), "f"(hh) : "memory");
            hbuf[pw][row_g][n_g] = hh;
            __syncwarp();
            if ((tid & 31) == 0) {
                asm volatile("mbarrier.arrive.release.cluster.shared::cluster.b64 _, [%0];"
                             :: "r"(peer_bar) : "memory");
            }
            {
                unsigned par = (unsigned)(s & 1);
                asm volatile(
                    "{\n\t"
                    ".reg .pred P1;\n\t"
                    "WLP%=:\n\t"
                    "mbarrier.try_wait.parity.acquire.cluster.shared::cta.b64 P1, [%0], %1, 0x989680;\n\t"
                    "@!P1 bra WLP%=;\n\t"
                    "}"
                    :: "r"(bar_addr), "r"(par) : "memory");
            }
            hbuf[pw][row_g][((r ^ 1) * 64) + nn_g] = land[pw][row_g][nn_g];
        }
        __syncthreads();

        if (is_gate) {
            py[(size_t)t * HH] = hlast;
            float xf0 = 0, xf1 = 0, xf2 = 0, xf3 = 0;
            if (s + 2 < CHUNK) {
                const float* p2 = px + (size_t)(t + 2) * G4;
                xf0 = p2[0]; xf1 = p2[128]; xf2 = p2[256]; xf3 = p2[384];
            }
            xc0 = xn0; xc1 = xn1; xc2 = xn2; xc3 = xn3;
            xn0 = xf0; xn1 = xf1; xn2 = xf2; xn3 = xf3;
        }
    }

    if (is_gate) {
        hstate[(b0 + row_g) * HH + n_g] = hlast;
        cstate[(b0 + row_g) * HH + n_g] = c;
    }
    asm volatile("barrier.cluster.arrive.aligned;" ::: "memory");
    asm volatile("barrier.cluster.wait.aligned;"   ::: "memory");
}

// ---------------------------------------------------------------------------
// Output projection: out[bt] = relu(y3[bt,:] . Wout + bout), one warp per row
// ---------------------------------------------------------------------------
__global__ __launch_bounds__(256)
void proj_kernel(const float* __restrict__ wout,
                 const float* __restrict__ bout,
                 float* __restrict__ out)
{
    int gwarp = (blockIdx.x * blockDim.x + threadIdx.x) >> 5;
    int lane  = threadIdx.x & 31;
    if (gwarp >= MROWS) return;
    float4 yv = ((const float4*)(g_y + (size_t)gwarp * HH))[lane];
    float4 wv = ((const float4*)wout)[lane];
    float s = yv.x * wv.x + yv.y * wv.y + yv.z * wv.z + yv.w * wv.w;
#pragma unroll
    for (int o = 16; o; o >>= 1) s += __shfl_xor_sync(0xFFFFFFFFu, s, o);
    if (lane == 0) out[gwarp] = fmaxf(s + bout[0], 0.f);
}

// ---------------------------------------------------------------------------
// Schedule (NCHUNK=8, 13 walls, <=2 jobs/wall; dependencies audited):
//  w0:(0,0) w1:(0,1)(1,0) w2:(0,2)(1,1) w3:(0,3)(2,0) w4:(0,4)(1,2)
//  w5:(0,5)(2,1) w6:(0,6)(1,3) w7:(0,7)(2,2) w8:(1,4)(2,3) w9:(1,5)(2,4)
//  w10:(1,6)(2,5) w11:(1,7)(2,6) w12:(2,7)
// gemm(l,c) placed after wall of (l-1,c), before wall of (l,c).
// ---------------------------------------------------------------------------
extern "C" void kernel_launch(void* const* d_in, const int* in_sizes, int n_in,
                              void* d_out, int out_size)
{
    const float* x    = (const float*)d_in[0];
    const float* h0   = (const float*)d_in[1];
    const float* c0   = (const float*)d_in[2];
    const float* Wih[3] = {(const float*)d_in[3], (const float*)d_in[7],  (const float*)d_in[11]};
    const float* Whh[3] = {(const float*)d_in[4], (const float*)d_in[8],  (const float*)d_in[12]};
    const float* bih[3] = {(const float*)d_in[5], (const float*)d_in[9],  (const float*)d_in[13]};
    const float* bhh[3] = {(const float*)d_in[6], (const float*)d_in[10], (const float*)d_in[14]};
    const float* Wout = (const float*)d_in[15];
    const float* bout = (const float*)d_in[16];

    float* out = (float*)d_out;           // [B*T]
    float* hN  = out + MROWS;             // [3,B,H] = live state + final output
    float* cN  = hN + 3 * BB * HH;

    init_state<<<(3 * BB * HH + 511) / 512, 512>>>(h0, c0, hN, cN);
    w_conv<<<(512 * 64 + 255) / 256, 256>>>(Wih[0], 0, 512 * 64);
    w_conv<<<(512 * 128 + 255) / 256, 256>>>(Wih[1], 1, 512 * 128);
    w_conv<<<(512 * 128 + 255) / 256, 256>>>(Wih[2], 2, 512 * 128);

    // layer-0 xg, full T: grid (4, 1024), lg=3
    xg_tf32<64><<<dim3(4, 1024), 256>>>(x, 0, 0, bih[0], bhh[0], 0, 3);

    const int C = CHUNK;
    auto rec1 = [&](int l0_, int t0_) {
        lstm_rec10<<<dim3(64, 1), 512>>>(Whh[0], Whh[1], Whh[2], hN, cN,
                                         make_int4(l0_, 0, 0, 0),
                                         make_int4(t0_, 0, 0, 0));
    };
    auto rec2 = [&](int la, int ta, int lb, int tb) {
        lstm_rec10<<<dim3(64, 2), 512>>>(Whh[0], Whh[1], Whh[2], hN, cN,
                                         make_int4(la, lb, 0, 0),
                                         make_int4(ta, tb, 0, 0));
    };
    auto gemm = [&](int l, int cc) {
        // one 128-row tile per batch row: grid (4, 128), lg=0
        xg_tf32<128><<<dim3(4, 128), 256>>>(nullptr, 1, l, bih[l], bhh[l],
                                            cc * C, 0);
    };

    rec1(0, 0);                                   // w0: (0,0)
    gemm(1, 0);
    rec2(0, 1 * C, 1, 0 * C);                     // w1: (0,1)(1,0)
    gemm(1, 1); gemm(2, 0);
    rec2(0, 2 * C, 1, 1 * C);                     // w2: (0,2)(1,1)
    gemm(1, 2); gemm(2, 1);
    rec2(0, 3 * C, 2, 0 * C);                     // w3: (0,3)(2,0)
    gemm(1, 3);
    rec2(0, 4 * C, 1, 2 * C);                     // w4: (0,4)(1,2)
    gemm(1, 4); gemm(2, 2);
    rec2(0, 5 * C, 2, 1 * C);                     // w5: (0,5)(2,1)
    gemm(1, 5);
    rec2(0, 6 * C, 1, 3 * C);                     // w6: (0,6)(1,3)
    gemm(1, 6); gemm(2, 3);
    rec2(0, 7 * C, 2, 2 * C);                     // w7: (0,7)(2,2)
    gemm(1, 7);
    rec2(1, 4 * C, 2, 3 * C);                     // w8: (1,4)(2,3)
    gemm(2, 4);
    rec2(1, 5 * C, 2, 4 * C);                     // w9: (1,5)(2,4)
    gemm(2, 5);
    rec2(1, 6 * C, 2, 5 * C);                     // w10: (1,6)(2,5)
    gemm(2, 6);
    rec2(1, 7 * C, 2, 6 * C);                     // w11: (1,7)(2,6)
    gemm(2, 7);
    rec1(2, 7 * C);                               // w12: (2,7)

    proj_kernel<<<MROWS / 8, 256>>>(Wout, bout, out);
}